// round 1
// baseline (speedup 1.0000x reference)
#include <cuda_runtime.h>
#include <cuda_bf16.h>
#include <cstdint>

#define N_PTS 8192
#define D_DIM 128

// Scratch (static device globals — no runtime allocation).
__device__ float g_XS[N_PTS * D_DIM];   // X @ S
__device__ float g_YS[N_PTS * D_DIM];   // Y @ S
__device__ float g_qX[N_PTS];           // x S x
__device__ float g_qY[N_PTS];           // y S y
__device__ float g_Apk[N_PTS * 256];    // rows: [YS_i | Y_i]
__device__ float g_Bpk[N_PTS * 256];    // rows: [X_j  | XS_j]

// ---------------------------------------------------------------------------
// Kernel 1: per-row S-multiply, quadratic forms, and operand packing.
// grid (8192, 2): y=0 -> X, y=1 -> Y. 128 threads = one output column each.
// ---------------------------------------------------------------------------
__global__ void prep_kernel(const float* __restrict__ X,
                            const float* __restrict__ Y,
                            const float* __restrict__ S) {
    const int i = blockIdx.x;
    const int t = threadIdx.x;
    const bool isY = (blockIdx.y != 0);
    const float* src = isY ? Y : X;

    __shared__ float row[D_DIM];
    __shared__ float red[D_DIM];

    const float rv = src[(size_t)i * D_DIM + t];
    row[t] = rv;
    __syncthreads();

    float acc = 0.f;
#pragma unroll 8
    for (int k = 0; k < D_DIM; k++)
        acc = fmaf(row[k], S[k * D_DIM + t], acc);   // (row @ S)[t]

    if (isY) {
        g_YS[(size_t)i * D_DIM + t] = acc;
        g_Apk[(size_t)i * 256 + t]       = acc;  // YS first half
        g_Apk[(size_t)i * 256 + 128 + t] = rv;   // Y  second half
    } else {
        g_XS[(size_t)i * D_DIM + t] = acc;
        g_Bpk[(size_t)i * 256 + t]       = rv;   // X  first half
        g_Bpk[(size_t)i * 256 + 128 + t] = acc;  // XS second half
    }

    // q = sum_t row[t] * acc[t]  (fixed-order tree reduction -> deterministic)
    red[t] = rv * acc;
    __syncthreads();
#pragma unroll
    for (int s = 64; s > 0; s >>= 1) {
        if (t < s) red[t] += red[t + s];
        __syncthreads();
    }
    if (t == 0) {
        if (isY) g_qY[i] = red[0];
        else     g_qX[i] = red[0];
    }
}

// ---------------------------------------------------------------------------
// Kernel 2: K[i][j] = exp(-0.5 * (qY_i + qX_j - dot(Apk_i, Bpk_j)))
// Classic 128x128 tile SGEMM (K=256), 256 threads, 8x8 micro-tile, fused exp.
// ---------------------------------------------------------------------------
__global__ __launch_bounds__(256, 2)
void cross_exp_kernel(float* __restrict__ Kout) {
    __shared__ float As[16][128];
    __shared__ float Bs[16][128];

    const int tid   = threadIdx.x;
    const int iBase = blockIdx.y * 128;
    const int jBase = blockIdx.x * 128;
    const int ty = tid >> 4;   // 0..15 -> row group
    const int tx = tid & 15;   // 0..15 -> col group

    float c[8][8];
#pragma unroll
    for (int u = 0; u < 8; u++)
#pragma unroll
        for (int v = 0; v < 8; v++) c[u][v] = 0.f;

    for (int kt = 0; kt < 256; kt += 16) {
#pragma unroll
        for (int r = 0; r < 2; r++) {
            const int id  = tid + r * 256;      // 0..511
            const int row = id >> 2;            // 0..127
            const int kg  = (id & 3) * 4;       // 0,4,8,12
            float4 a = *(const float4*)&g_Apk[(size_t)(iBase + row) * 256 + kt + kg];
            As[kg + 0][row] = a.x; As[kg + 1][row] = a.y;
            As[kg + 2][row] = a.z; As[kg + 3][row] = a.w;
            float4 b = *(const float4*)&g_Bpk[(size_t)(jBase + row) * 256 + kt + kg];
            Bs[kg + 0][row] = b.x; Bs[kg + 1][row] = b.y;
            Bs[kg + 2][row] = b.z; Bs[kg + 3][row] = b.w;
        }
        __syncthreads();

#pragma unroll
        for (int k = 0; k < 16; k++) {
            float a[8], b[8];
            *(float4*)(a)     = *(const float4*)&As[k][ty * 8];
            *(float4*)(a + 4) = *(const float4*)&As[k][ty * 8 + 4];
            *(float4*)(b)     = *(const float4*)&Bs[k][tx * 8];
            *(float4*)(b + 4) = *(const float4*)&Bs[k][tx * 8 + 4];
#pragma unroll
            for (int u = 0; u < 8; u++)
#pragma unroll
                for (int v = 0; v < 8; v++)
                    c[u][v] = fmaf(a[u], b[v], c[u][v]);
        }
        __syncthreads();
    }

    float qy[8], qx[8];
#pragma unroll
    for (int u = 0; u < 8; u++) qy[u] = g_qY[iBase + ty * 8 + u];
#pragma unroll
    for (int v = 0; v < 8; v++) qx[v] = g_qX[jBase + tx * 8 + v];

#pragma unroll
    for (int u = 0; u < 8; u++) {
        const size_t o = (size_t)(iBase + ty * 8 + u) * N_PTS + jBase + tx * 8;
        float4 r0, r1;
        r0.x = __expf(0.5f * (c[u][0] - qy[u] - qx[0]));
        r0.y = __expf(0.5f * (c[u][1] - qy[u] - qx[1]));
        r0.z = __expf(0.5f * (c[u][2] - qy[u] - qx[2]));
        r0.w = __expf(0.5f * (c[u][3] - qy[u] - qx[3]));
        r1.x = __expf(0.5f * (c[u][4] - qy[u] - qx[4]));
        r1.y = __expf(0.5f * (c[u][5] - qy[u] - qx[5]));
        r1.z = __expf(0.5f * (c[u][6] - qy[u] - qx[6]));
        r1.w = __expf(0.5f * (c[u][7] - qy[u] - qx[7]));
        *(float4*)&Kout[o]     = r0;
        *(float4*)&Kout[o + 4] = r1;
    }
}

// ---------------------------------------------------------------------------
// Kernel 3: dK[i][d] = 2 * (rowsum_i * YS[i][d] - sum_j K[i][j] * XS[j][d])
// 32 rows per block, full 128 cols. rowsum computed redundantly per-thread
// with fixed order (deterministic, no atomics).
// ---------------------------------------------------------------------------
__global__ __launch_bounds__(256, 2)
void dk_kernel(const float* __restrict__ K, float* __restrict__ dK) {
    __shared__ float Ks[32][33];
    __shared__ float Xs[32][128];

    const int tid   = threadIdx.x;
    const int iBase = blockIdx.x * 32;
    const int ty = tid >> 5;  // 0..7  -> rows ty*4 .. ty*4+3
    const int tx = tid & 31;  // 0..31 -> cols tx + 32*v

    float acc[4][4];
    float rs[4];
#pragma unroll
    for (int u = 0; u < 4; u++) {
        rs[u] = 0.f;
#pragma unroll
        for (int v = 0; v < 4; v++) acc[u][v] = 0.f;
    }

    for (int jb = 0; jb < N_PTS; jb += 32) {
#pragma unroll
        for (int l = 0; l < 4; l++) {
            const int id = tid + l * 256;
            Ks[id >> 5][id & 31] = K[(size_t)(iBase + (id >> 5)) * N_PTS + jb + (id & 31)];
        }
#pragma unroll
        for (int l = 0; l < 16; l++) {
            const int id = tid + l * 256;
            Xs[id >> 7][id & 127] = g_XS[(size_t)(jb + (id >> 7)) * D_DIM + (id & 127)];
        }
        __syncthreads();

#pragma unroll 8
        for (int jj = 0; jj < 32; jj++) {
            float xv[4];
#pragma unroll
            for (int v = 0; v < 4; v++) xv[v] = Xs[jj][tx + 32 * v];
#pragma unroll
            for (int u = 0; u < 4; u++) {
                const float kv = Ks[ty * 4 + u][jj];
                rs[u] += kv;
#pragma unroll
                for (int v = 0; v < 4; v++)
                    acc[u][v] = fmaf(kv, xv[v], acc[u][v]);
            }
        }
        __syncthreads();
    }

#pragma unroll
    for (int u = 0; u < 4; u++) {
        const int i = iBase + ty * 4 + u;
#pragma unroll
        for (int v = 0; v < 4; v++) {
            const int d = tx + 32 * v;
            dK[(size_t)i * D_DIM + d] =
                2.0f * (rs[u] * g_YS[(size_t)i * D_DIM + d] - acc[u][v]);
        }
    }
}

// ---------------------------------------------------------------------------
extern "C" void kernel_launch(void* const* d_in, const int* in_sizes, int n_in,
                              void* d_out, int out_size) {
    const float* X = (const float*)d_in[0];
    const float* Y = (const float*)d_in[1];
    const float* S = (const float*)d_in[2];
    float* out = (float*)d_out;
    float* Kout  = out;                                   // [8192 x 8192]
    float* dKout = out + (size_t)N_PTS * N_PTS;           // [8192 x 128]

    dim3 gp(N_PTS, 2);
    prep_kernel<<<gp, 128>>>(X, Y, S);

    dim3 gm(N_PTS / 128, N_PTS / 128);
    cross_exp_kernel<<<gm, 256>>>(Kout);

    dk_kernel<<<N_PTS / 32, 256>>>(Kout, dKout);
}

// round 2
// speedup vs baseline: 1.0005x; 1.0005x over previous
#include <cuda_runtime.h>
#include <cuda_bf16.h>
#include <cstdint>

#define N_PTS 8192
#define D_DIM 128

// Scratch (static device globals — no runtime allocation).
__device__ float g_XS[N_PTS * D_DIM];   // X @ S
__device__ float g_YS[N_PTS * D_DIM];   // Y @ S
__device__ float g_qX[N_PTS];           // x S x
__device__ float g_qY[N_PTS];           // y S y
__device__ float g_Apk[N_PTS * 256];    // rows: [YS_i | Y_i]
__device__ float g_Bpk[N_PTS * 256];    // rows: [X_j  | XS_j]

// ---------------------------------------------------------------------------
// Kernel 1: per-row S-multiply, quadratic forms, and operand packing.
// grid (8192, 2): y=0 -> X, y=1 -> Y. 128 threads = one output column each.
// ---------------------------------------------------------------------------
__global__ void prep_kernel(const float* __restrict__ X,
                            const float* __restrict__ Y,
                            const float* __restrict__ S) {
    const int i = blockIdx.x;
    const int t = threadIdx.x;
    const bool isY = (blockIdx.y != 0);
    const float* src = isY ? Y : X;

    __shared__ float row[D_DIM];
    __shared__ float red[D_DIM];

    const float rv = src[(size_t)i * D_DIM + t];
    row[t] = rv;
    __syncthreads();

    float acc = 0.f;
#pragma unroll 8
    for (int k = 0; k < D_DIM; k++)
        acc = fmaf(row[k], S[k * D_DIM + t], acc);   // (row @ S)[t]

    if (isY) {
        g_YS[(size_t)i * D_DIM + t] = acc;
        g_Apk[(size_t)i * 256 + t]       = acc;  // YS first half
        g_Apk[(size_t)i * 256 + 128 + t] = rv;   // Y  second half
    } else {
        g_XS[(size_t)i * D_DIM + t] = acc;
        g_Bpk[(size_t)i * 256 + t]       = rv;   // X  first half
        g_Bpk[(size_t)i * 256 + 128 + t] = acc;  // XS second half
    }

    // q = sum_t row[t] * acc[t]  (fixed-order tree reduction -> deterministic)
    red[t] = rv * acc;
    __syncthreads();
#pragma unroll
    for (int s = 64; s > 0; s >>= 1) {
        if (t < s) red[t] += red[t + s];
        __syncthreads();
    }
    if (t == 0) {
        if (isY) g_qY[i] = red[0];
        else     g_qX[i] = red[0];
    }
}

// ---------------------------------------------------------------------------
// Kernel 2: K[i][j] = exp(-0.5 * (qY_i + qX_j - dot(Apk_i, Bpk_j)))
// Classic 128x128 tile SGEMM (K=256), 256 threads, 8x8 micro-tile, fused exp.
// ---------------------------------------------------------------------------
__global__ __launch_bounds__(256, 2)
void cross_exp_kernel(float* __restrict__ Kout) {
    __shared__ float As[16][128];
    __shared__ float Bs[16][128];

    const int tid   = threadIdx.x;
    const int iBase = blockIdx.y * 128;
    const int jBase = blockIdx.x * 128;
    const int ty = tid >> 4;   // 0..15 -> row group
    const int tx = tid & 15;   // 0..15 -> col group

    float c[8][8];
#pragma unroll
    for (int u = 0; u < 8; u++)
#pragma unroll
        for (int v = 0; v < 8; v++) c[u][v] = 0.f;

    for (int kt = 0; kt < 256; kt += 16) {
#pragma unroll
        for (int r = 0; r < 2; r++) {
            const int id  = tid + r * 256;      // 0..511
            const int row = id >> 2;            // 0..127
            const int kg  = (id & 3) * 4;       // 0,4,8,12
            float4 a = *(const float4*)&g_Apk[(size_t)(iBase + row) * 256 + kt + kg];
            As[kg + 0][row] = a.x; As[kg + 1][row] = a.y;
            As[kg + 2][row] = a.z; As[kg + 3][row] = a.w;
            float4 b = *(const float4*)&g_Bpk[(size_t)(jBase + row) * 256 + kt + kg];
            Bs[kg + 0][row] = b.x; Bs[kg + 1][row] = b.y;
            Bs[kg + 2][row] = b.z; Bs[kg + 3][row] = b.w;
        }
        __syncthreads();

#pragma unroll
        for (int k = 0; k < 16; k++) {
            float a[8], b[8];
            *(float4*)(a)     = *(const float4*)&As[k][ty * 8];
            *(float4*)(a + 4) = *(const float4*)&As[k][ty * 8 + 4];
            *(float4*)(b)     = *(const float4*)&Bs[k][tx * 8];
            *(float4*)(b + 4) = *(const float4*)&Bs[k][tx * 8 + 4];
#pragma unroll
            for (int u = 0; u < 8; u++)
#pragma unroll
                for (int v = 0; v < 8; v++)
                    c[u][v] = fmaf(a[u], b[v], c[u][v]);
        }
        __syncthreads();
    }

    float qy[8], qx[8];
#pragma unroll
    for (int u = 0; u < 8; u++) qy[u] = g_qY[iBase + ty * 8 + u];
#pragma unroll
    for (int v = 0; v < 8; v++) qx[v] = g_qX[jBase + tx * 8 + v];

#pragma unroll
    for (int u = 0; u < 8; u++) {
        const size_t o = (size_t)(iBase + ty * 8 + u) * N_PTS + jBase + tx * 8;
        float4 r0, r1;
        r0.x = __expf(0.5f * (c[u][0] - qy[u] - qx[0]));
        r0.y = __expf(0.5f * (c[u][1] - qy[u] - qx[1]));
        r0.z = __expf(0.5f * (c[u][2] - qy[u] - qx[2]));
        r0.w = __expf(0.5f * (c[u][3] - qy[u] - qx[3]));
        r1.x = __expf(0.5f * (c[u][4] - qy[u] - qx[4]));
        r1.y = __expf(0.5f * (c[u][5] - qy[u] - qx[5]));
        r1.z = __expf(0.5f * (c[u][6] - qy[u] - qx[6]));
        r1.w = __expf(0.5f * (c[u][7] - qy[u] - qx[7]));
        *(float4*)&Kout[o]     = r0;
        *(float4*)&Kout[o + 4] = r1;
    }
}

// ---------------------------------------------------------------------------
// Kernel 3: dK[i][d] = 2 * (rowsum_i * YS[i][d] - sum_j K[i][j] * XS[j][d])
// 32 rows per block, full 128 cols. rowsum computed redundantly per-thread
// with fixed order (deterministic, no atomics).
// ---------------------------------------------------------------------------
__global__ __launch_bounds__(256, 2)
void dk_kernel(const float* __restrict__ K, float* __restrict__ dK) {
    __shared__ float Ks[32][33];
    __shared__ float Xs[32][128];

    const int tid   = threadIdx.x;
    const int iBase = blockIdx.x * 32;
    const int ty = tid >> 5;  // 0..7  -> rows ty*4 .. ty*4+3
    const int tx = tid & 31;  // 0..31 -> cols tx + 32*v

    float acc[4][4];
    float rs[4];
#pragma unroll
    for (int u = 0; u < 4; u++) {
        rs[u] = 0.f;
#pragma unroll
        for (int v = 0; v < 4; v++) acc[u][v] = 0.f;
    }

    for (int jb = 0; jb < N_PTS; jb += 32) {
#pragma unroll
        for (int l = 0; l < 4; l++) {
            const int id = tid + l * 256;
            Ks[id >> 5][id & 31] = K[(size_t)(iBase + (id >> 5)) * N_PTS + jb + (id & 31)];
        }
#pragma unroll
        for (int l = 0; l < 16; l++) {
            const int id = tid + l * 256;
            Xs[id >> 7][id & 127] = g_XS[(size_t)(jb + (id >> 7)) * D_DIM + (id & 127)];
        }
        __syncthreads();

#pragma unroll 8
        for (int jj = 0; jj < 32; jj++) {
            float xv[4];
#pragma unroll
            for (int v = 0; v < 4; v++) xv[v] = Xs[jj][tx + 32 * v];
#pragma unroll
            for (int u = 0; u < 4; u++) {
                const float kv = Ks[ty * 4 + u][jj];
                rs[u] += kv;
#pragma unroll
                for (int v = 0; v < 4; v++)
                    acc[u][v] = fmaf(kv, xv[v], acc[u][v]);
            }
        }
        __syncthreads();
    }

#pragma unroll
    for (int u = 0; u < 4; u++) {
        const int i = iBase + ty * 4 + u;
#pragma unroll
        for (int v = 0; v < 4; v++) {
            const int d = tx + 32 * v;
            dK[(size_t)i * D_DIM + d] =
                2.0f * (rs[u] * g_YS[(size_t)i * D_DIM + d] - acc[u][v]);
        }
    }
}

// ---------------------------------------------------------------------------
extern "C" void kernel_launch(void* const* d_in, const int* in_sizes, int n_in,
                              void* d_out, int out_size) {
    const float* X = (const float*)d_in[0];
    const float* Y = (const float*)d_in[1];
    const float* S = (const float*)d_in[2];
    float* out = (float*)d_out;
    float* Kout  = out;                                   // [8192 x 8192]
    float* dKout = out + (size_t)N_PTS * N_PTS;           // [8192 x 128]

    dim3 gp(N_PTS, 2);
    prep_kernel<<<gp, 128>>>(X, Y, S);

    dim3 gm(N_PTS / 128, N_PTS / 128);
    cross_exp_kernel<<<gm, 256>>>(Kout);

    dk_kernel<<<N_PTS / 32, 256>>>(Kout, dKout);
}

// round 4
// speedup vs baseline: 2.6266x; 2.6253x over previous
#include <cuda_runtime.h>
#include <cuda_bf16.h>
#include <cstdint>

#define NP 8192
#define DD 128

// ---------------- device scratch ----------------
__device__ uint16_t g_A768[(size_t)NP * 768];   // i rows: [ahYS|ahY | ahYS|ahY | alYS|alY]
__device__ uint16_t g_B768[(size_t)NP * 768];   // j rows: [bhX|bhXS | blX|blXS | bhX|bhXS]
__device__ uint16_t g_Xh[(size_t)NP * DD];      // XS hi limb, row-major [j][d]
__device__ uint16_t g_Xl[(size_t)NP * DD];      // XS lo limb
__device__ float    g_YS[(size_t)NP * DD];
__device__ float    g_qX[NP];
__device__ float    g_qY[NP];
__device__ float    g_rsp[(size_t)4 * NP];      // rowsum partials per j-slice
__device__ float    g_rowsum[NP];
__device__ float    g_dkp[(size_t)4 * NP * DD]; // dP partials per j-slice

// ---------------- helpers ----------------
__device__ __forceinline__ uint32_t smem_u32(const void* p) {
    uint32_t a;
    asm("{ .reg .u64 t; cvta.to.shared.u64 t, %1; cvt.u32.u64 %0, t; }" : "=r"(a) : "l"(p));
    return a;
}
__device__ __forceinline__ uint32_t swz(uint32_t x) { return x ^ ((x >> 3) & 0x70); }

#define CP_ASYNC16(dst, src) \
    asm volatile("cp.async.cg.shared.global [%0], [%1], 16;" :: "r"(dst), "l"(src) : "memory")
#define CP_COMMIT() asm volatile("cp.async.commit_group;" ::: "memory")
#define CP_WAIT2()  asm volatile("cp.async.wait_group 2;" ::: "memory")

__device__ __forceinline__ void ldsm_x4(uint32_t& r0, uint32_t& r1, uint32_t& r2,
                                        uint32_t& r3, uint32_t addr) {
    asm volatile("ldmatrix.sync.aligned.m8n8.x4.shared.b16 {%0,%1,%2,%3}, [%4];"
                 : "=r"(r0), "=r"(r1), "=r"(r2), "=r"(r3) : "r"(addr));
}
__device__ __forceinline__ void ldsm_x4t(uint32_t& r0, uint32_t& r1, uint32_t& r2,
                                         uint32_t& r3, uint32_t addr) {
    asm volatile("ldmatrix.sync.aligned.m8n8.x4.trans.shared.b16 {%0,%1,%2,%3}, [%4];"
                 : "=r"(r0), "=r"(r1), "=r"(r2), "=r"(r3) : "r"(addr));
}
__device__ __forceinline__ void mma16816(float* c, uint32_t a0, uint32_t a1, uint32_t a2,
                                         uint32_t a3, uint32_t b0, uint32_t b1) {
    asm volatile(
        "mma.sync.aligned.m16n8k16.row.col.f32.bf16.bf16.f32 "
        "{%0,%1,%2,%3}, {%4,%5,%6,%7}, {%8,%9}, {%0,%1,%2,%3};"
        : "+f"(c[0]), "+f"(c[1]), "+f"(c[2]), "+f"(c[3])
        : "r"(a0), "r"(a1), "r"(a2), "r"(a3), "r"(b0), "r"(b1));
}
__device__ __forceinline__ uint32_t pack2(float a, float b) {
    __nv_bfloat162 h = __floats2bfloat162_rn(a, b);
    return *(uint32_t*)&h;
}

// SMEM layout (dynamic) for fused kernel
#define SM_A     0u            // 3 x 16KB slabs: A [128m][64k]
#define SM_B     49152u        // 3 x 16KB slabs: B [128j][64k]
#define SM_XH    98304u        // 2 panels x 16KB: XSh [128j][64d]
#define SM_XL    131072u
#define SM_QX    163840u
#define SM_QY    164352u
#define SM_TOTAL 164864

// ===========================================================================
// prep: XS/YS, quadratic forms, limb-packed operands. 16 X + 16 Y rows/block.
// ===========================================================================
__global__ __launch_bounds__(256, 1)
void prep_kernel(const float* __restrict__ X, const float* __restrict__ Y,
                 const float* __restrict__ S) {
    extern __shared__ char sm[];
    float* Ss   = (float*)sm;                  // 64KB
    float* rows = (float*)(sm + 65536);        // 16KB
    float* qtmp = (float*)(sm + 81920);

    const int tid = threadIdx.x;
    const int wid = tid >> 5, lane = tid & 31;
    const int rowBase = blockIdx.x * 16;

    for (int idx = tid; idx < 16384; idx += 256) Ss[idx] = S[idx];
    for (int idx = tid; idx < 4096; idx += 256) {
        int r = idx >> 7, c = idx & 127;
        rows[idx] = (r < 16) ? X[(size_t)(rowBase + r) * DD + c]
                             : Y[(size_t)(rowBase + r - 16) * DD + c];
    }
    __syncthreads();

    const int side = tid >> 7;   // 0 = X, 1 = Y
    const int c    = tid & 127;

    for (int r = 0; r < 16; r++) {
        const float* rv = rows + (side * 16 + r) * DD;
        float acc = 0.f;
#pragma unroll 16
        for (int k = 0; k < DD; k++) acc = fmaf(rv[k], Ss[k * DD + c], acc);
        const float xv = rv[c];
        const int i = rowBase + r;

        __nv_bfloat16 hs = __float2bfloat16(acc);
        __nv_bfloat16 ls = __float2bfloat16(acc - __bfloat162float(hs));
        __nv_bfloat16 hv = __float2bfloat16(xv);
        __nv_bfloat16 lv = __float2bfloat16(xv - __bfloat162float(hv));
        uint16_t uhs = __bfloat16_as_ushort(hs), uls = __bfloat16_as_ushort(ls);
        uint16_t uhv = __bfloat16_as_ushort(hv), ulv = __bfloat16_as_ushort(lv);

        const size_t b = (size_t)i * 768;
        if (side == 0) {
            g_B768[b + c]       = uhv;  g_B768[b + 128 + c] = uhs;
            g_B768[b + 256 + c] = ulv;  g_B768[b + 384 + c] = uls;
            g_B768[b + 512 + c] = uhv;  g_B768[b + 640 + c] = uhs;
            g_Xh[(size_t)i * DD + c] = uhs;
            g_Xl[(size_t)i * DD + c] = uls;
        } else {
            g_A768[b + c]       = uhs;  g_A768[b + 128 + c] = uhv;
            g_A768[b + 256 + c] = uhs;  g_A768[b + 384 + c] = uhv;
            g_A768[b + 512 + c] = uls;  g_A768[b + 640 + c] = ulv;
            g_YS[(size_t)i * DD + c] = acc;
        }

        float p = xv * acc;
#pragma unroll
        for (int o = 16; o > 0; o >>= 1) p += __shfl_down_sync(0xffffffffu, p, o);
        if (lane == 0) qtmp[wid] = p;
        __syncthreads();
        if (c == 0) {
            float q = qtmp[side * 4] + qtmp[side * 4 + 1] +
                      qtmp[side * 4 + 2] + qtmp[side * 4 + 3];
            if (side) g_qY[i] = q; else g_qX[i] = q;
        }
        __syncthreads();
    }
}

// ===========================================================================
// fused: K tile (GEMM1 K=768) + exp + dP accumulation (GEMM2, limb phases).
// CTA: i-tile 128 x j-slice 2048 (16 chunks of 128). 8 warps, warp = m16.
// ===========================================================================
__global__ __launch_bounds__(256, 1)
void fused_kernel(float* __restrict__ Kout) {
    extern __shared__ char sm[];
    const uint32_t sb = smem_u32(sm);
    float* qx_s = (float*)(sm + SM_QX);
    float* qy_s = (float*)(sm + SM_QY);

    const int tid  = threadIdx.x;
    const int w    = tid >> 5, lane = tid & 31;
    const int r    = lane >> 2, cp2 = lane & 3;
    const int iBase  = blockIdx.x * 128;
    const int slice  = blockIdx.y;
    const int jBase0 = slice * 2048;

    if (tid < 128) qy_s[tid] = g_qY[iBase + tid];

    const int row0 = iBase + w * 16 + r;
    const int lrow = (lane & 15);
    const int lcg  = (lane >> 4) * 16;

    float dP[16][4];
#pragma unroll
    for (int t = 0; t < 16; t++)
#pragma unroll
        for (int v = 0; v < 4; v++) dP[t][v] = 0.f;
    float rs0 = 0.f, rs1 = 0.f;

    for (int ch = 0; ch < 16; ch++) {
        const int jBase = jBase0 + ch * 128;
        __syncthreads();   // previous chunk's consumers done with xs/qx/slabs

        // group 0: XS panels + qx
        {
#pragma unroll
            for (int k = 0; k < 16; k++) {
                int u = tid + k * 256;
                int limb = u >> 11, rem = u & 2047;
                int p = rem >> 10, wi = rem & 1023;
                int row = wi >> 3, seg = wi & 7;
                uint32_t dst = sb + (limb ? SM_XL : SM_XH) + p * 16384u +
                               swz((uint32_t)(row * 128 + seg * 16));
                const uint16_t* src = (limb ? g_Xl : g_Xh) +
                                      (size_t)(jBase + row) * DD + p * 64 + seg * 8;
                CP_ASYNC16(dst, src);
            }
            if (tid < 32) CP_ASYNC16(sb + SM_QX + tid * 16, g_qX + jBase + tid * 4);
        }
        CP_COMMIT();

        // groups 1,2: slabs 0,1
#pragma unroll
        for (int s0 = 0; s0 < 2; s0++) {
#pragma unroll
            for (int k = 0; k < 4; k++) {
                int u = tid + k * 256, row = u >> 3, seg = u & 7;
                CP_ASYNC16(sb + SM_A + s0 * 16384u + swz((uint32_t)(row * 128 + seg * 16)),
                           g_A768 + (size_t)(iBase + row) * 768 + s0 * 64 + seg * 8);
                CP_ASYNC16(sb + SM_B + s0 * 16384u + swz((uint32_t)(row * 128 + seg * 16)),
                           g_B768 + (size_t)(jBase + row) * 768 + s0 * 64 + seg * 8);
            }
            CP_COMMIT();
        }

        float c[16][4];
#pragma unroll
        for (int t = 0; t < 16; t++)
#pragma unroll
            for (int v = 0; v < 4; v++) c[t][v] = 0.f;

        for (int s = 0; s < 12; s++) {
            if (s + 2 < 12) {
                const int sp = s + 2, buf = sp % 3;
#pragma unroll
                for (int k = 0; k < 4; k++) {
                    int u = tid + k * 256, row = u >> 3, seg = u & 7;
                    CP_ASYNC16(sb + SM_A + buf * 16384u + swz((uint32_t)(row * 128 + seg * 16)),
                               g_A768 + (size_t)(iBase + row) * 768 + sp * 64 + seg * 8);
                    CP_ASYNC16(sb + SM_B + buf * 16384u + swz((uint32_t)(row * 128 + seg * 16)),
                               g_B768 + (size_t)(jBase + row) * 768 + sp * 64 + seg * 8);
                }
            }
            CP_COMMIT();
            CP_WAIT2();
            __syncthreads();

            const uint32_t aB = sb + SM_A + (uint32_t)(s % 3) * 16384u;
            const uint32_t bB = sb + SM_B + (uint32_t)(s % 3) * 16384u;
#pragma unroll
            for (int kk = 0; kk < 4; kk++) {
                uint32_t a0, a1, a2, a3;
                ldsm_x4(a0, a1, a2, a3,
                        aB + swz((uint32_t)((w * 16 + lrow) * 128 + kk * 32 + lcg)));
#pragma unroll
                for (int g = 0; g < 8; g++) {
                    uint32_t b0, b1, b2, b3;
                    ldsm_x4(b0, b1, b2, b3,
                            bB + swz((uint32_t)((g * 16 + lrow) * 128 + kk * 32 + lcg)));
                    mma16816(c[2 * g],     a0, a1, a2, a3, b0, b2);
                    mma16816(c[2 * g + 1], a0, a1, a2, a3, b1, b3);
                }
            }
            __syncthreads();
        }

        // ---- epilogue: exp, K write, limb fragments ----
        const float qy0 = qy_s[w * 16 + r], qy1 = qy_s[w * 16 + r + 8];
        uint32_t khp[16][2], klp[16][2];
#pragma unroll
        for (int t = 0; t < 16; t++) {
            const int jl = t * 8 + cp2 * 2;
            const float qx0 = qx_s[jl], qx1 = qx_s[jl + 1];
            float k00 = __expf(0.5f * (c[t][0] - qy0 - qx0));
            float k01 = __expf(0.5f * (c[t][1] - qy0 - qx1));
            float k10 = __expf(0.5f * (c[t][2] - qy1 - qx0));
            float k11 = __expf(0.5f * (c[t][3] - qy1 - qx1));
            rs0 += k00 + k01;
            rs1 += k10 + k11;
            *(float2*)&Kout[(size_t)row0 * NP + jBase + jl]       = make_float2(k00, k01);
            *(float2*)&Kout[(size_t)(row0 + 8) * NP + jBase + jl] = make_float2(k10, k11);

            __nv_bfloat16 h00 = __float2bfloat16(k00), h01 = __float2bfloat16(k01);
            __nv_bfloat16 h10 = __float2bfloat16(k10), h11 = __float2bfloat16(k11);
            khp[t][0] = (uint32_t)__bfloat16_as_ushort(h00) |
                        ((uint32_t)__bfloat16_as_ushort(h01) << 16);
            khp[t][1] = (uint32_t)__bfloat16_as_ushort(h10) |
                        ((uint32_t)__bfloat16_as_ushort(h11) << 16);
            klp[t][0] = pack2(k00 - __bfloat162float(h00), k01 - __bfloat162float(h01));
            klp[t][1] = pack2(k10 - __bfloat162float(h10), k11 - __bfloat162float(h11));
        }

        // ---- GEMM2: dP += Kh*Xh + Kh*Xl + Kl*Xh ----
#pragma unroll
        for (int kt = 0; kt < 8; kt++) {
            const uint32_t ah0 = khp[2 * kt][0], ah1 = khp[2 * kt][1];
            const uint32_t ah2 = khp[2 * kt + 1][0], ah3 = khp[2 * kt + 1][1];
            const uint32_t al0 = klp[2 * kt][0], al1 = klp[2 * kt][1];
            const uint32_t al2 = klp[2 * kt + 1][0], al3 = klp[2 * kt + 1][1];
#pragma unroll
            for (int gd = 0; gd < 8; gd++) {
                const uint32_t off = (uint32_t)(gd >> 2) * 16384u +
                    swz((uint32_t)((kt * 16 + lrow) * 128 + (gd & 3) * 32 + lcg));
                uint32_t bh0, bh1, bh2, bh3, bl0, bl1, bl2, bl3;
                ldsm_x4t(bh0, bh1, bh2, bh3, sb + SM_XH + off);
                ldsm_x4t(bl0, bl1, bl2, bl3, sb + SM_XL + off);
                mma16816(dP[2 * gd],     ah0, ah1, ah2, ah3, bh0, bh1);
                mma16816(dP[2 * gd + 1], ah0, ah1, ah2, ah3, bh2, bh3);
                mma16816(dP[2 * gd],     ah0, ah1, ah2, ah3, bl0, bl1);
                mma16816(dP[2 * gd + 1], ah0, ah1, ah2, ah3, bl2, bl3);
                mma16816(dP[2 * gd],     al0, al1, al2, al3, bh0, bh1);
                mma16816(dP[2 * gd + 1], al0, al1, al2, al3, bh2, bh3);
            }
        }
    }

    // ---- write dP partials + rowsum partials ----
#pragma unroll
    for (int t = 0; t < 16; t++) {
        const int d = t * 8 + cp2 * 2;
        float* o0 = g_dkp + (size_t)slice * NP * DD + (size_t)row0 * DD + d;
        float* o1 = g_dkp + (size_t)slice * NP * DD + (size_t)(row0 + 8) * DD + d;
        *(float2*)o0 = make_float2(dP[t][0], dP[t][1]);
        *(float2*)o1 = make_float2(dP[t][2], dP[t][3]);
    }
    rs0 += __shfl_xor_sync(0xffffffffu, rs0, 1);
    rs0 += __shfl_xor_sync(0xffffffffu, rs0, 2);
    rs1 += __shfl_xor_sync(0xffffffffu, rs1, 1);
    rs1 += __shfl_xor_sync(0xffffffffu, rs1, 2);
    if (cp2 == 0) {
        g_rsp[(size_t)slice * NP + row0]     = rs0;
        g_rsp[(size_t)slice * NP + row0 + 8] = rs1;
    }
}

// ===========================================================================
__global__ void rowsum_reduce_kernel() {
    const int i = blockIdx.x * 256 + threadIdx.x;
    float s = ((g_rsp[i] + g_rsp[NP + i]) + (g_rsp[2 * NP + i] + g_rsp[3 * NP + i]));
    g_rowsum[i] = s;
}

__global__ void dk_final_kernel(float* __restrict__ dK) {
    const size_t idx = (size_t)blockIdx.x * 256 + threadIdx.x;
    const size_t i = idx >> 7;
    float p = ((g_dkp[idx] + g_dkp[(size_t)NP * DD + idx]) +
               (g_dkp[2 * (size_t)NP * DD + idx] + g_dkp[3 * (size_t)NP * DD + idx]));
    dK[idx] = 2.0f * (g_rowsum[i] * g_YS[idx] - p);
}

// ===========================================================================
extern "C" void kernel_launch(void* const* d_in, const int* in_sizes, int n_in,
                              void* d_out, int out_size) {
    (void)in_sizes; (void)n_in; (void)out_size;
    const float* X = (const float*)d_in[0];
    const float* Y = (const float*)d_in[1];
    const float* S = (const float*)d_in[2];
    float* out   = (float*)d_out;
    float* Kout  = out;
    float* dKout = out + (size_t)NP * NP;

    const int SM_PREP = 81952;
    cudaFuncSetAttribute(prep_kernel,  cudaFuncAttributeMaxDynamicSharedMemorySize, SM_PREP);
    cudaFuncSetAttribute(fused_kernel, cudaFuncAttributeMaxDynamicSharedMemorySize, SM_TOTAL);

    prep_kernel<<<NP / 16, 256, SM_PREP>>>(X, Y, S);

    dim3 gf(NP / 128, 4);
    fused_kernel<<<gf, 256, SM_TOTAL>>>(Kout);

    rowsum_reduce_kernel<<<NP / 256, 256>>>();
    dk_final_kernel<<<(NP * DD) / 256, 256>>>(dKout);
}

// round 5
// speedup vs baseline: 3.6652x; 1.3954x over previous
#include <cuda_runtime.h>
#include <cuda_bf16.h>
#include <cstdint>

#define NP 8192
#define DD 128
#define NSLICE 8
#define JSLICE 1024

// ---------------- device scratch ----------------
__device__ uint16_t g_A384[(size_t)NP * 384];   // i rows: [ah(YS) | ah(YS) | al(YS)]
__device__ uint16_t g_B384[(size_t)NP * 384];   // j rows: [bh(X)  | bl(X)  | bh(X) ]
__device__ uint16_t g_Xh[(size_t)NP * DD];      // XS hi limb, row-major [j][d]
__device__ uint16_t g_Xl[(size_t)NP * DD];      // XS lo limb
__device__ float    g_YS[(size_t)NP * DD];
__device__ float    g_qX[NP];
__device__ float    g_qY[NP];
__device__ float    g_rsp[(size_t)NSLICE * NP];
__device__ float    g_rowsum[NP];
__device__ float    g_dkp[(size_t)NSLICE * NP * DD];

// ---------------- helpers ----------------
__device__ __forceinline__ uint32_t smem_u32(const void* p) {
    uint32_t a;
    asm("{ .reg .u64 t; cvta.to.shared.u64 t, %1; cvt.u32.u64 %0, t; }" : "=r"(a) : "l"(p));
    return a;
}
__device__ __forceinline__ uint32_t swz(uint32_t x) { return x ^ ((x >> 3) & 0x70); }

#define CP_ASYNC16(dst, src) \
    asm volatile("cp.async.cg.shared.global [%0], [%1], 16;" :: "r"(dst), "l"(src) : "memory")
#define CP_COMMIT() asm volatile("cp.async.commit_group;" ::: "memory")
#define CP_WAIT2()  asm volatile("cp.async.wait_group 2;" ::: "memory")

__device__ __forceinline__ void ldsm_x4(uint32_t& r0, uint32_t& r1, uint32_t& r2,
                                        uint32_t& r3, uint32_t addr) {
    asm volatile("ldmatrix.sync.aligned.m8n8.x4.shared.b16 {%0,%1,%2,%3}, [%4];"
                 : "=r"(r0), "=r"(r1), "=r"(r2), "=r"(r3) : "r"(addr));
}
__device__ __forceinline__ void ldsm_x4t(uint32_t& r0, uint32_t& r1, uint32_t& r2,
                                         uint32_t& r3, uint32_t addr) {
    asm volatile("ldmatrix.sync.aligned.m8n8.x4.trans.shared.b16 {%0,%1,%2,%3}, [%4];"
                 : "=r"(r0), "=r"(r1), "=r"(r2), "=r"(r3) : "r"(addr));
}
__device__ __forceinline__ void mma16816(float* c, uint32_t a0, uint32_t a1, uint32_t a2,
                                         uint32_t a3, uint32_t b0, uint32_t b1) {
    asm volatile(
        "mma.sync.aligned.m16n8k16.row.col.f32.bf16.bf16.f32 "
        "{%0,%1,%2,%3}, {%4,%5,%6,%7}, {%8,%9}, {%0,%1,%2,%3};"
        : "+f"(c[0]), "+f"(c[1]), "+f"(c[2]), "+f"(c[3])
        : "r"(a0), "r"(a1), "r"(a2), "r"(a3), "r"(b0), "r"(b1));
}
__device__ __forceinline__ uint32_t pack2(float a, float b) {
    __nv_bfloat162 h = __floats2bfloat162_rn(a, b);
    return *(uint32_t*)&h;
}

// SMEM layout (dynamic) for fused kernel
#define SM_A     0u            // 3 x 16KB slabs: A [128m][64k]
#define SM_B     49152u        // 3 x 16KB slabs: B [128j][64k]
#define SM_XH    98304u        // 2 panels x 16KB: XSh [128j][64d]
#define SM_XL    131072u
#define SM_QX    163840u
#define SM_QY    164352u
#define SM_TOTAL 164864

// ===========================================================================
// prep: XS/YS, quadratic forms, limb-packed operands. 16 X + 16 Y rows/block.
// ===========================================================================
__global__ __launch_bounds__(256, 1)
void prep_kernel(const float* __restrict__ X, const float* __restrict__ Y,
                 const float* __restrict__ S) {
    extern __shared__ char sm[];
    float* Ss   = (float*)sm;                  // 64KB
    float* rows = (float*)(sm + 65536);        // 16KB
    float* qtmp = (float*)(sm + 81920);

    const int tid = threadIdx.x;
    const int wid = tid >> 5, lane = tid & 31;
    const int rowBase = blockIdx.x * 16;

    for (int idx = tid; idx < 16384; idx += 256) Ss[idx] = S[idx];
    for (int idx = tid; idx < 4096; idx += 256) {
        int r = idx >> 7, c = idx & 127;
        rows[idx] = (r < 16) ? X[(size_t)(rowBase + r) * DD + c]
                             : Y[(size_t)(rowBase + r - 16) * DD + c];
    }
    __syncthreads();

    const int side = tid >> 7;   // 0 = X, 1 = Y
    const int c    = tid & 127;

    for (int r = 0; r < 16; r++) {
        const float* rv = rows + (side * 16 + r) * DD;
        float acc = 0.f;
#pragma unroll 16
        for (int k = 0; k < DD; k++) acc = fmaf(rv[k], Ss[k * DD + c], acc);
        const float xv = rv[c];
        const int i = rowBase + r;

        __nv_bfloat16 hs = __float2bfloat16(acc);
        __nv_bfloat16 ls = __float2bfloat16(acc - __bfloat162float(hs));
        __nv_bfloat16 hv = __float2bfloat16(xv);
        __nv_bfloat16 lv = __float2bfloat16(xv - __bfloat162float(hv));
        uint16_t uhs = __bfloat16_as_ushort(hs), uls = __bfloat16_as_ushort(ls);
        uint16_t uhv = __bfloat16_as_ushort(hv), ulv = __bfloat16_as_ushort(lv);

        const size_t b = (size_t)i * 384;
        if (side == 0) {
            // B = X limbs: [bh | bl | bh]
            g_B384[b + c]       = uhv;
            g_B384[b + 128 + c] = ulv;
            g_B384[b + 256 + c] = uhv;
            g_Xh[(size_t)i * DD + c] = uhs;   // XS limbs for GEMM2
            g_Xl[(size_t)i * DD + c] = uls;
        } else {
            // A = YS limbs: [ah | ah | al]
            g_A384[b + c]       = uhs;
            g_A384[b + 128 + c] = uhs;
            g_A384[b + 256 + c] = uls;
            g_YS[(size_t)i * DD + c] = acc;
        }

        float p = xv * acc;
#pragma unroll
        for (int o = 16; o > 0; o >>= 1) p += __shfl_down_sync(0xffffffffu, p, o);
        if (lane == 0) qtmp[wid] = p;
        __syncthreads();
        if (c == 0) {
            float q = qtmp[side * 4] + qtmp[side * 4 + 1] +
                      qtmp[side * 4 + 2] + qtmp[side * 4 + 3];
            if (side) g_qY[i] = q; else g_qX[i] = q;
        }
        __syncthreads();
    }
}

// ===========================================================================
// fused: quad cross (GEMM1, K=384, symmetric-S: quad = qY+qX-2*YS.X) + exp
//        + dP accumulation (GEMM2, 3 limb phases).
// CTA: i-tile 128 x j-slice 1024 (8 chunks of 128). 8 warps, warp = m16.
// ===========================================================================
__global__ __launch_bounds__(256, 1)
void fused_kernel(float* __restrict__ Kout) {
    extern __shared__ char sm[];
    const uint32_t sb = smem_u32(sm);
    float* qx_s = (float*)(sm + SM_QX);
    float* qy_s = (float*)(sm + SM_QY);

    const int tid  = threadIdx.x;
    const int w    = tid >> 5, lane = tid & 31;
    const int r    = lane >> 2, cp2 = lane & 3;
    const int iBase  = blockIdx.x * 128;
    const int slice  = blockIdx.y;
    const int jBase0 = slice * JSLICE;

    if (tid < 128) qy_s[tid] = 0.5f * g_qY[iBase + tid];

    const int row0 = iBase + w * 16 + r;
    const int lrow = (lane & 15);
    const int lcg  = (lane >> 4) * 16;

    float dP[16][4];
#pragma unroll
    for (int t = 0; t < 16; t++)
#pragma unroll
        for (int v = 0; v < 4; v++) dP[t][v] = 0.f;
    float rs0 = 0.f, rs1 = 0.f;

    for (int ch = 0; ch < JSLICE / 128; ch++) {
        const int jBase = jBase0 + ch * 128;
        __syncthreads();   // previous chunk's consumers done with xs/qx/slabs

        // group 0: XS panels + qx
        {
#pragma unroll
            for (int k = 0; k < 16; k++) {
                int u = tid + k * 256;
                int limb = u >> 11, rem = u & 2047;
                int p = rem >> 10, wi = rem & 1023;
                int row = wi >> 3, seg = wi & 7;
                uint32_t dst = sb + (limb ? SM_XL : SM_XH) + p * 16384u +
                               swz((uint32_t)(row * 128 + seg * 16));
                const uint16_t* src = (limb ? g_Xl : g_Xh) +
                                      (size_t)(jBase + row) * DD + p * 64 + seg * 8;
                CP_ASYNC16(dst, src);
            }
            if (tid < 32) CP_ASYNC16(sb + SM_QX + tid * 16, g_qX + jBase + tid * 4);
        }
        CP_COMMIT();

        // groups 1,2: slabs 0,1
#pragma unroll
        for (int s0 = 0; s0 < 2; s0++) {
#pragma unroll
            for (int k = 0; k < 4; k++) {
                int u = tid + k * 256, row = u >> 3, seg = u & 7;
                CP_ASYNC16(sb + SM_A + s0 * 16384u + swz((uint32_t)(row * 128 + seg * 16)),
                           g_A384 + (size_t)(iBase + row) * 384 + s0 * 64 + seg * 8);
                CP_ASYNC16(sb + SM_B + s0 * 16384u + swz((uint32_t)(row * 128 + seg * 16)),
                           g_B384 + (size_t)(jBase + row) * 384 + s0 * 64 + seg * 8);
            }
            CP_COMMIT();
        }

        float c[16][4];
#pragma unroll
        for (int t = 0; t < 16; t++)
#pragma unroll
            for (int v = 0; v < 4; v++) c[t][v] = 0.f;

        for (int s = 0; s < 6; s++) {
            if (s + 2 < 6) {
                const int sp = s + 2, buf = sp % 3;
#pragma unroll
                for (int k = 0; k < 4; k++) {
                    int u = tid + k * 256, row = u >> 3, seg = u & 7;
                    CP_ASYNC16(sb + SM_A + buf * 16384u + swz((uint32_t)(row * 128 + seg * 16)),
                               g_A384 + (size_t)(iBase + row) * 384 + sp * 64 + seg * 8);
                    CP_ASYNC16(sb + SM_B + buf * 16384u + swz((uint32_t)(row * 128 + seg * 16)),
                               g_B384 + (size_t)(jBase + row) * 384 + sp * 64 + seg * 8);
                }
            }
            CP_COMMIT();
            CP_WAIT2();
            __syncthreads();

            const uint32_t aB = sb + SM_A + (uint32_t)(s % 3) * 16384u;
            const uint32_t bB = sb + SM_B + (uint32_t)(s % 3) * 16384u;
#pragma unroll
            for (int kk = 0; kk < 4; kk++) {
                uint32_t a0, a1, a2, a3;
                ldsm_x4(a0, a1, a2, a3,
                        aB + swz((uint32_t)((w * 16 + lrow) * 128 + kk * 32 + lcg)));
#pragma unroll
                for (int g = 0; g < 8; g++) {
                    uint32_t b0, b1, b2, b3;
                    ldsm_x4(b0, b1, b2, b3,
                            bB + swz((uint32_t)((g * 16 + lrow) * 128 + kk * 32 + lcg)));
                    mma16816(c[2 * g],     a0, a1, a2, a3, b0, b2);
                    mma16816(c[2 * g + 1], a0, a1, a2, a3, b1, b3);
                }
            }
            __syncthreads();
        }

        // ---- epilogue: K = exp(dot - 0.5*(qY+qX)), limb fragments ----
        const float qy0 = qy_s[w * 16 + r], qy1 = qy_s[w * 16 + r + 8];
        uint32_t khp[16][2], klp[16][2];
#pragma unroll
        for (int t = 0; t < 16; t++) {
            const int jl = t * 8 + cp2 * 2;
            const float qx0 = 0.5f * qx_s[jl], qx1 = 0.5f * qx_s[jl + 1];
            float k00 = __expf(c[t][0] - qy0 - qx0);
            float k01 = __expf(c[t][1] - qy0 - qx1);
            float k10 = __expf(c[t][2] - qy1 - qx0);
            float k11 = __expf(c[t][3] - qy1 - qx1);
            rs0 += k00 + k01;
            rs1 += k10 + k11;
            *(float2*)&Kout[(size_t)row0 * NP + jBase + jl]       = make_float2(k00, k01);
            *(float2*)&Kout[(size_t)(row0 + 8) * NP + jBase + jl] = make_float2(k10, k11);

            __nv_bfloat16 h00 = __float2bfloat16(k00), h01 = __float2bfloat16(k01);
            __nv_bfloat16 h10 = __float2bfloat16(k10), h11 = __float2bfloat16(k11);
            khp[t][0] = (uint32_t)__bfloat16_as_ushort(h00) |
                        ((uint32_t)__bfloat16_as_ushort(h01) << 16);
            khp[t][1] = (uint32_t)__bfloat16_as_ushort(h10) |
                        ((uint32_t)__bfloat16_as_ushort(h11) << 16);
            klp[t][0] = pack2(k00 - __bfloat162float(h00), k01 - __bfloat162float(h01));
            klp[t][1] = pack2(k10 - __bfloat162float(h10), k11 - __bfloat162float(h11));
        }

        // ---- GEMM2: dP += Kh*Xh + Kh*Xl + Kl*Xh ----
#pragma unroll
        for (int kt = 0; kt < 8; kt++) {
            const uint32_t ah0 = khp[2 * kt][0], ah1 = khp[2 * kt][1];
            const uint32_t ah2 = khp[2 * kt + 1][0], ah3 = khp[2 * kt + 1][1];
            const uint32_t al0 = klp[2 * kt][0], al1 = klp[2 * kt][1];
            const uint32_t al2 = klp[2 * kt + 1][0], al3 = klp[2 * kt + 1][1];
#pragma unroll
            for (int gd = 0; gd < 8; gd++) {
                const uint32_t off = (uint32_t)(gd >> 2) * 16384u +
                    swz((uint32_t)((kt * 16 + lrow) * 128 + (gd & 3) * 32 + lcg));
                uint32_t bh0, bh1, bh2, bh3, bl0, bl1, bl2, bl3;
                ldsm_x4t(bh0, bh1, bh2, bh3, sb + SM_XH + off);
                ldsm_x4t(bl0, bl1, bl2, bl3, sb + SM_XL + off);
                mma16816(dP[2 * gd],     ah0, ah1, ah2, ah3, bh0, bh1);
                mma16816(dP[2 * gd + 1], ah0, ah1, ah2, ah3, bh2, bh3);
                mma16816(dP[2 * gd],     ah0, ah1, ah2, ah3, bl0, bl1);
                mma16816(dP[2 * gd + 1], ah0, ah1, ah2, ah3, bl2, bl3);
                mma16816(dP[2 * gd],     al0, al1, al2, al3, bh0, bh1);
                mma16816(dP[2 * gd + 1], al0, al1, al2, al3, bh2, bh3);
            }
        }
    }

    // ---- write dP partials + rowsum partials ----
#pragma unroll
    for (int t = 0; t < 16; t++) {
        const int d = t * 8 + cp2 * 2;
        float* o0 = g_dkp + (size_t)slice * NP * DD + (size_t)row0 * DD + d;
        float* o1 = g_dkp + (size_t)slice * NP * DD + (size_t)(row0 + 8) * DD + d;
        *(float2*)o0 = make_float2(dP[t][0], dP[t][1]);
        *(float2*)o1 = make_float2(dP[t][2], dP[t][3]);
    }
    rs0 += __shfl_xor_sync(0xffffffffu, rs0, 1);
    rs0 += __shfl_xor_sync(0xffffffffu, rs0, 2);
    rs1 += __shfl_xor_sync(0xffffffffu, rs1, 1);
    rs1 += __shfl_xor_sync(0xffffffffu, rs1, 2);
    if (cp2 == 0) {
        g_rsp[(size_t)slice * NP + row0]     = rs0;
        g_rsp[(size_t)slice * NP + row0 + 8] = rs1;
    }
}

// ===========================================================================
__global__ void rowsum_reduce_kernel() {
    const int i = blockIdx.x * 256 + threadIdx.x;
    float s = 0.f;
#pragma unroll
    for (int h = 0; h < NSLICE; h++) s += g_rsp[(size_t)h * NP + i];
    g_rowsum[i] = s;
}

__global__ void dk_final_kernel(float* __restrict__ dK) {
    const size_t idx = (size_t)blockIdx.x * 256 + threadIdx.x;
    const size_t i = idx >> 7;
    float p = 0.f;
#pragma unroll
    for (int h = 0; h < NSLICE; h++) p += g_dkp[(size_t)h * NP * DD + idx];
    dK[idx] = 2.0f * (g_rowsum[i] * g_YS[idx] - p);
}

// ===========================================================================
extern "C" void kernel_launch(void* const* d_in, const int* in_sizes, int n_in,
                              void* d_out, int out_size) {
    (void)in_sizes; (void)n_in; (void)out_size;
    const float* X = (const float*)d_in[0];
    const float* Y = (const float*)d_in[1];
    const float* S = (const float*)d_in[2];
    float* out   = (float*)d_out;
    float* Kout  = out;
    float* dKout = out + (size_t)NP * NP;

    const int SM_PREP = 81952;
    cudaFuncSetAttribute(prep_kernel,  cudaFuncAttributeMaxDynamicSharedMemorySize, SM_PREP);
    cudaFuncSetAttribute(fused_kernel, cudaFuncAttributeMaxDynamicSharedMemorySize, SM_TOTAL);

    prep_kernel<<<NP / 16, 256, SM_PREP>>>(X, Y, S);

    dim3 gf(NP / 128, NSLICE);
    fused_kernel<<<gf, 256, SM_TOTAL>>>(Kout);

    rowsum_reduce_kernel<<<NP / 256, 256>>>();
    dk_final_kernel<<<(NP * DD) / 256, 256>>>(dKout);
}

// round 6
// speedup vs baseline: 4.3142x; 1.1771x over previous
#include <cuda_runtime.h>
#include <cuda_bf16.h>
#include <cstdint>

#define NP 8192
#define DD 128
#define NSLICE 8
#define JSLICE 1024

// ---------------- device scratch ----------------
__device__ uint16_t g_A384[(size_t)NP * 384];   // i rows: [ah(YS) | ah(YS) | al(YS)]
__device__ uint16_t g_B384[(size_t)NP * 384];   // j rows: [bh(X)  | bl(X)  | bh(X) ]
__device__ uint16_t g_Xh[(size_t)NP * DD];      // XS hi limb, row-major [j][d]
__device__ float    g_YS[(size_t)NP * DD];
__device__ float    g_qX[NP];
__device__ float    g_qY[NP];
__device__ float    g_rsp[(size_t)NSLICE * NP];
__device__ float    g_dkp[(size_t)NSLICE * NP * DD];

// ---------------- helpers ----------------
__device__ __forceinline__ uint32_t smem_u32(const void* p) {
    uint32_t a;
    asm("{ .reg .u64 t; cvta.to.shared.u64 t, %1; cvt.u32.u64 %0, t; }" : "=r"(a) : "l"(p));
    return a;
}
__device__ __forceinline__ uint32_t swz(uint32_t x) { return x ^ ((x >> 3) & 0x70); }

#define CP_ASYNC16(dst, src) \
    asm volatile("cp.async.cg.shared.global [%0], [%1], 16;" :: "r"(dst), "l"(src) : "memory")
#define CP_COMMIT() asm volatile("cp.async.commit_group;" ::: "memory")
#define CP_WAIT2()  asm volatile("cp.async.wait_group 2;" ::: "memory")

__device__ __forceinline__ void ldsm_x4(uint32_t& r0, uint32_t& r1, uint32_t& r2,
                                        uint32_t& r3, uint32_t addr) {
    asm volatile("ldmatrix.sync.aligned.m8n8.x4.shared.b16 {%0,%1,%2,%3}, [%4];"
                 : "=r"(r0), "=r"(r1), "=r"(r2), "=r"(r3) : "r"(addr));
}
__device__ __forceinline__ void ldsm_x4t(uint32_t& r0, uint32_t& r1, uint32_t& r2,
                                         uint32_t& r3, uint32_t addr) {
    asm volatile("ldmatrix.sync.aligned.m8n8.x4.trans.shared.b16 {%0,%1,%2,%3}, [%4];"
                 : "=r"(r0), "=r"(r1), "=r"(r2), "=r"(r3) : "r"(addr));
}
__device__ __forceinline__ void mma16816(float* c, uint32_t a0, uint32_t a1, uint32_t a2,
                                         uint32_t a3, uint32_t b0, uint32_t b1) {
    asm volatile(
        "mma.sync.aligned.m16n8k16.row.col.f32.bf16.bf16.f32 "
        "{%0,%1,%2,%3}, {%4,%5,%6,%7}, {%8,%9}, {%0,%1,%2,%3};"
        : "+f"(c[0]), "+f"(c[1]), "+f"(c[2]), "+f"(c[3])
        : "r"(a0), "r"(a1), "r"(a2), "r"(a3), "r"(b0), "r"(b1));
}
__device__ __forceinline__ uint32_t pack2(float a, float b) {
    __nv_bfloat162 h = __floats2bfloat162_rn(a, b);
    return *(uint32_t*)&h;
}

// SMEM layout (dynamic) for fused kernel
#define SM_A     0u            // 3 x 16KB slabs: A [128m][64k]
#define SM_B     49152u        // 3 x 16KB slabs: B [128j][64k]
#define SM_XH    98304u        // 2 panels x 16KB: XSh [128j][64d]
#define SM_QX    131072u
#define SM_QY    131584u
#define SM_TOTAL 132096

// ===========================================================================
// prep: XS/YS, quadratic forms, limb-packed operands. 16 X + 16 Y rows/block.
// ===========================================================================
__global__ __launch_bounds__(256, 1)
void prep_kernel(const float* __restrict__ X, const float* __restrict__ Y,
                 const float* __restrict__ S) {
    extern __shared__ char sm[];
    float* Ss   = (float*)sm;                  // 64KB
    float* rows = (float*)(sm + 65536);        // 16KB
    float* qtmp = (float*)(sm + 81920);

    const int tid = threadIdx.x;
    const int wid = tid >> 5, lane = tid & 31;
    const int rowBase = blockIdx.x * 16;

    for (int idx = tid; idx < 16384; idx += 256) Ss[idx] = S[idx];
    for (int idx = tid; idx < 4096; idx += 256) {
        int r = idx >> 7, c = idx & 127;
        rows[idx] = (r < 16) ? X[(size_t)(rowBase + r) * DD + c]
                             : Y[(size_t)(rowBase + r - 16) * DD + c];
    }
    __syncthreads();

    const int side = tid >> 7;   // 0 = X, 1 = Y
    const int c    = tid & 127;

    for (int r = 0; r < 16; r++) {
        const float* rv = rows + (side * 16 + r) * DD;
        float acc = 0.f;
#pragma unroll 16
        for (int k = 0; k < DD; k++) acc = fmaf(rv[k], Ss[k * DD + c], acc);
        const float xv = rv[c];
        const int i = rowBase + r;

        __nv_bfloat16 hs = __float2bfloat16(acc);
        __nv_bfloat16 ls = __float2bfloat16(acc - __bfloat162float(hs));
        __nv_bfloat16 hv = __float2bfloat16(xv);
        __nv_bfloat16 lv = __float2bfloat16(xv - __bfloat162float(hv));
        uint16_t uhs = __bfloat16_as_ushort(hs), uls = __bfloat16_as_ushort(ls);
        uint16_t uhv = __bfloat16_as_ushort(hv), ulv = __bfloat16_as_ushort(lv);

        const size_t b = (size_t)i * 384;
        if (side == 0) {
            // B = X limbs: [bh | bl | bh]
            g_B384[b + c]       = uhv;
            g_B384[b + 128 + c] = ulv;
            g_B384[b + 256 + c] = uhv;
            g_Xh[(size_t)i * DD + c] = uhs;   // XS hi limb for GEMM2
        } else {
            // A = YS limbs: [ah | ah | al]
            g_A384[b + c]       = uhs;
            g_A384[b + 128 + c] = uhs;
            g_A384[b + 256 + c] = uls;
            g_YS[(size_t)i * DD + c] = acc;
        }

        float p = xv * acc;
#pragma unroll
        for (int o = 16; o > 0; o >>= 1) p += __shfl_down_sync(0xffffffffu, p, o);
        if (lane == 0) qtmp[wid] = p;
        __syncthreads();
        if (c == 0) {
            float q = qtmp[side * 4] + qtmp[side * 4 + 1] +
                      qtmp[side * 4 + 2] + qtmp[side * 4 + 3];
            if (side) g_qY[i] = q; else g_qX[i] = q;
        }
        __syncthreads();
    }
}

// ===========================================================================
// fused: quad cross (GEMM1, K=384, symmetric S) + exp + dP (GEMM2, Kh@Xh).
// CTA: i-tile 128 x j-slice 1024 (8 chunks of 128). 8 warps, warp = m16.
// ===========================================================================
__global__ __launch_bounds__(256, 1)
void fused_kernel(float* __restrict__ Kout) {
    extern __shared__ char sm[];
    const uint32_t sb = smem_u32(sm);
    float* qx_s = (float*)(sm + SM_QX);
    float* qy_s = (float*)(sm + SM_QY);

    const int tid  = threadIdx.x;
    const int w    = tid >> 5, lane = tid & 31;
    const int r    = lane >> 2, cp2 = lane & 3;
    const int iBase  = blockIdx.x * 128;
    const int slice  = blockIdx.y;
    const int jBase0 = slice * JSLICE;

    if (tid < 128) qy_s[tid] = 0.5f * g_qY[iBase + tid];

    const int row0 = iBase + w * 16 + r;
    const int lrow = (lane & 15);
    const int lcg  = (lane >> 4) * 16;

    float dP[16][4];
#pragma unroll
    for (int t = 0; t < 16; t++)
#pragma unroll
        for (int v = 0; v < 4; v++) dP[t][v] = 0.f;
    float rs0 = 0.f, rs1 = 0.f;

    for (int ch = 0; ch < JSLICE / 128; ch++) {
        const int jBase = jBase0 + ch * 128;
        __syncthreads();   // previous chunk's consumers done with xh/qx/slabs

        // group 0: XSh panels + qx
        {
#pragma unroll
            for (int k = 0; k < 8; k++) {
                int u = tid + k * 256;
                int p = u >> 10, wi = u & 1023;
                int row = wi >> 3, seg = wi & 7;
                uint32_t dst = sb + SM_XH + p * 16384u +
                               swz((uint32_t)(row * 128 + seg * 16));
                const uint16_t* src = g_Xh + (size_t)(jBase + row) * DD + p * 64 + seg * 8;
                CP_ASYNC16(dst, src);
            }
            if (tid < 32) CP_ASYNC16(sb + SM_QX + tid * 16, g_qX + jBase + tid * 4);
        }
        CP_COMMIT();

        // groups 1,2: slabs 0,1
#pragma unroll
        for (int s0 = 0; s0 < 2; s0++) {
#pragma unroll
            for (int k = 0; k < 4; k++) {
                int u = tid + k * 256, row = u >> 3, seg = u & 7;
                CP_ASYNC16(sb + SM_A + s0 * 16384u + swz((uint32_t)(row * 128 + seg * 16)),
                           g_A384 + (size_t)(iBase + row) * 384 + s0 * 64 + seg * 8);
                CP_ASYNC16(sb + SM_B + s0 * 16384u + swz((uint32_t)(row * 128 + seg * 16)),
                           g_B384 + (size_t)(jBase + row) * 384 + s0 * 64 + seg * 8);
            }
            CP_COMMIT();
        }

        float c[16][4];
#pragma unroll
        for (int t = 0; t < 16; t++)
#pragma unroll
            for (int v = 0; v < 4; v++) c[t][v] = 0.f;

        for (int s = 0; s < 6; s++) {
            if (s + 2 < 6) {
                const int sp = s + 2, buf = sp % 3;
#pragma unroll
                for (int k = 0; k < 4; k++) {
                    int u = tid + k * 256, row = u >> 3, seg = u & 7;
                    CP_ASYNC16(sb + SM_A + buf * 16384u + swz((uint32_t)(row * 128 + seg * 16)),
                               g_A384 + (size_t)(iBase + row) * 384 + sp * 64 + seg * 8);
                    CP_ASYNC16(sb + SM_B + buf * 16384u + swz((uint32_t)(row * 128 + seg * 16)),
                               g_B384 + (size_t)(jBase + row) * 384 + sp * 64 + seg * 8);
                }
            }
            CP_COMMIT();
            CP_WAIT2();
            __syncthreads();

            const uint32_t aB = sb + SM_A + (uint32_t)(s % 3) * 16384u;
            const uint32_t bB = sb + SM_B + (uint32_t)(s % 3) * 16384u;
#pragma unroll
            for (int kk = 0; kk < 4; kk++) {
                uint32_t a0, a1, a2, a3;
                ldsm_x4(a0, a1, a2, a3,
                        aB + swz((uint32_t)((w * 16 + lrow) * 128 + kk * 32 + lcg)));
#pragma unroll
                for (int g = 0; g < 8; g++) {
                    uint32_t b0, b1, b2, b3;
                    ldsm_x4(b0, b1, b2, b3,
                            bB + swz((uint32_t)((g * 16 + lrow) * 128 + kk * 32 + lcg)));
                    mma16816(c[2 * g],     a0, a1, a2, a3, b0, b2);
                    mma16816(c[2 * g + 1], a0, a1, a2, a3, b1, b3);
                }
            }
            __syncthreads();
        }

        // ---- epilogue: K = exp(dot - 0.5*(qY+qX)), Kh fragments ----
        const float qy0 = qy_s[w * 16 + r], qy1 = qy_s[w * 16 + r + 8];
        uint32_t khp[16][2];
#pragma unroll
        for (int t = 0; t < 16; t++) {
            const int jl = t * 8 + cp2 * 2;
            const float qx0 = 0.5f * qx_s[jl], qx1 = 0.5f * qx_s[jl + 1];
            float k00 = __expf(c[t][0] - qy0 - qx0);
            float k01 = __expf(c[t][1] - qy0 - qx1);
            float k10 = __expf(c[t][2] - qy1 - qx0);
            float k11 = __expf(c[t][3] - qy1 - qx1);
            rs0 += k00 + k01;
            rs1 += k10 + k11;
            *(float2*)&Kout[(size_t)row0 * NP + jBase + jl]       = make_float2(k00, k01);
            *(float2*)&Kout[(size_t)(row0 + 8) * NP + jBase + jl] = make_float2(k10, k11);
            khp[t][0] = pack2(k00, k01);
            khp[t][1] = pack2(k10, k11);
        }

        // ---- GEMM2: dP += Kh @ Xh ----
#pragma unroll
        for (int kt = 0; kt < 8; kt++) {
            const uint32_t ah0 = khp[2 * kt][0], ah1 = khp[2 * kt][1];
            const uint32_t ah2 = khp[2 * kt + 1][0], ah3 = khp[2 * kt + 1][1];
#pragma unroll
            for (int gd = 0; gd < 8; gd++) {
                const uint32_t off = (uint32_t)(gd >> 2) * 16384u +
                    swz((uint32_t)((kt * 16 + lrow) * 128 + (gd & 3) * 32 + lcg));
                uint32_t bh0, bh1, bh2, bh3;
                ldsm_x4t(bh0, bh1, bh2, bh3, sb + SM_XH + off);
                mma16816(dP[2 * gd],     ah0, ah1, ah2, ah3, bh0, bh1);
                mma16816(dP[2 * gd + 1], ah0, ah1, ah2, ah3, bh2, bh3);
            }
        }
    }

    // ---- write dP partials + rowsum partials ----
#pragma unroll
    for (int t = 0; t < 16; t++) {
        const int d = t * 8 + cp2 * 2;
        float* o0 = g_dkp + (size_t)slice * NP * DD + (size_t)row0 * DD + d;
        float* o1 = g_dkp + (size_t)slice * NP * DD + (size_t)(row0 + 8) * DD + d;
        *(float2*)o0 = make_float2(dP[t][0], dP[t][1]);
        *(float2*)o1 = make_float2(dP[t][2], dP[t][3]);
    }
    rs0 += __shfl_xor_sync(0xffffffffu, rs0, 1);
    rs0 += __shfl_xor_sync(0xffffffffu, rs0, 2);
    rs1 += __shfl_xor_sync(0xffffffffu, rs1, 1);
    rs1 += __shfl_xor_sync(0xffffffffu, rs1, 2);
    if (cp2 == 0) {
        g_rsp[(size_t)slice * NP + row0]     = rs0;
        g_rsp[(size_t)slice * NP + row0 + 8] = rs1;
    }
}

// ===========================================================================
__global__ void dk_final_kernel(float* __restrict__ dK) {
    const size_t idx = (size_t)blockIdx.x * 256 + threadIdx.x;
    const size_t i = idx >> 7;
    float s = 0.f, p = 0.f;
#pragma unroll
    for (int h = 0; h < NSLICE; h++) {
        s += g_rsp[(size_t)h * NP + i];
        p += g_dkp[(size_t)h * NP * DD + idx];
    }
    dK[idx] = 2.0f * (s * g_YS[idx] - p);
}

// ===========================================================================
extern "C" void kernel_launch(void* const* d_in, const int* in_sizes, int n_in,
                              void* d_out, int out_size) {
    (void)in_sizes; (void)n_in; (void)out_size;
    const float* X = (const float*)d_in[0];
    const float* Y = (const float*)d_in[1];
    const float* S = (const float*)d_in[2];
    float* out   = (float*)d_out;
    float* Kout  = out;
    float* dKout = out + (size_t)NP * NP;

    const int SM_PREP = 81952;
    cudaFuncSetAttribute(prep_kernel,  cudaFuncAttributeMaxDynamicSharedMemorySize, SM_PREP);
    cudaFuncSetAttribute(fused_kernel, cudaFuncAttributeMaxDynamicSharedMemorySize, SM_TOTAL);

    prep_kernel<<<NP / 16, 256, SM_PREP>>>(X, Y, S);

    dim3 gf(NP / 128, NSLICE);
    fused_kernel<<<gf, 256, SM_TOTAL>>>(Kout);

    dk_final_kernel<<<(NP * DD) / 256, 256>>>(dKout);
}

// round 7
// speedup vs baseline: 8.4412x; 1.9566x over previous
#include <cuda_runtime.h>
#include <cuda_fp16.h>
#include <cstdint>

#define NP 8192
#define DD 128
#define NSLICE 8
#define JSLICE 1024

// ---------------- device scratch ----------------
__device__ uint16_t g_Ah[(size_t)NP * DD];      // YS fp16, row-major [i][d]
__device__ uint16_t g_Bh[(size_t)NP * DD];      // X  fp16, row-major [j][d]
__device__ uint16_t g_Xh[(size_t)NP * DD];      // XS fp16, row-major [j][d]
__device__ float    g_YS[(size_t)NP * DD];
__device__ float    g_qX[NP];
__device__ float    g_qY[NP];
__device__ float    g_rsp[(size_t)NSLICE * NP];
__device__ float    g_dkp[(size_t)NSLICE * NP * DD];

// ---------------- helpers ----------------
__device__ __forceinline__ uint32_t smem_u32(const void* p) {
    uint32_t a;
    asm("{ .reg .u64 t; cvta.to.shared.u64 t, %1; cvt.u32.u64 %0, t; }" : "=r"(a) : "l"(p));
    return a;
}
__device__ __forceinline__ uint32_t swz(uint32_t x) { return x ^ ((x >> 3) & 0x70); }

#define CP_ASYNC16(dst, src) \
    asm volatile("cp.async.cg.shared.global [%0], [%1], 16;" :: "r"(dst), "l"(src) : "memory")
#define CP_COMMIT() asm volatile("cp.async.commit_group;" ::: "memory")
#define CP_WAIT1()  asm volatile("cp.async.wait_group 1;" ::: "memory")

__device__ __forceinline__ void ldsm_x4(uint32_t& r0, uint32_t& r1, uint32_t& r2,
                                        uint32_t& r3, uint32_t addr) {
    asm volatile("ldmatrix.sync.aligned.m8n8.x4.shared.b16 {%0,%1,%2,%3}, [%4];"
                 : "=r"(r0), "=r"(r1), "=r"(r2), "=r"(r3) : "r"(addr));
}
__device__ __forceinline__ void ldsm_x4t(uint32_t& r0, uint32_t& r1, uint32_t& r2,
                                         uint32_t& r3, uint32_t addr) {
    asm volatile("ldmatrix.sync.aligned.m8n8.x4.trans.shared.b16 {%0,%1,%2,%3}, [%4];"
                 : "=r"(r0), "=r"(r1), "=r"(r2), "=r"(r3) : "r"(addr));
}
__device__ __forceinline__ void mma16816(float* c, uint32_t a0, uint32_t a1, uint32_t a2,
                                         uint32_t a3, uint32_t b0, uint32_t b1) {
    asm volatile(
        "mma.sync.aligned.m16n8k16.row.col.f32.f16.f16.f32 "
        "{%0,%1,%2,%3}, {%4,%5,%6,%7}, {%8,%9}, {%0,%1,%2,%3};"
        : "+f"(c[0]), "+f"(c[1]), "+f"(c[2]), "+f"(c[3])
        : "r"(a0), "r"(a1), "r"(a2), "r"(a3), "r"(b0), "r"(b1));
}
__device__ __forceinline__ uint32_t pack2h(float a, float b) {
    __half2 h = __floats2half2_rn(a, b);
    return *(uint32_t*)&h;
}

// SMEM layout: A panel (chunk-invariant) + double-buffered B/XH/qx
#define SM_A     0u              // 32 KB: YSh [128][128] fp16, 2 half-slabs of 16KB
#define SM_B     32768u          // 2 bufs x 32 KB: Xh panel
#define SM_XH    98304u          // 2 bufs x 32 KB: XSh panel
#define SM_QX    163840u         // 2 bufs x 512
#define SM_QY    164864u         // 512
#define SM_TOTAL 165376

// ===========================================================================
// prep: 8 X rows + 8 Y rows per block, 128 threads (one per column).
// S streamed from L2 (coalesced); rows broadcast from SMEM.
// ===========================================================================
__global__ __launch_bounds__(128, 8)
void prep_kernel(const float* __restrict__ X, const float* __restrict__ Y,
                 const float* __restrict__ S) {
    __shared__ float rows[16][DD];
    __shared__ float parts[4][16];

    const int c = threadIdx.x;
    const int wid = c >> 5, lane = c & 31;
    const int rowBase = blockIdx.x * 8;

#pragma unroll
    for (int r = 0; r < 8; r++) {
        rows[r][c]     = X[(size_t)(rowBase + r) * DD + c];
        rows[8 + r][c] = Y[(size_t)(rowBase + r) * DD + c];
    }
    __syncthreads();

    float acc[16];
#pragma unroll
    for (int r = 0; r < 16; r++) acc[r] = 0.f;

    for (int k = 0; k < DD; k += 4) {
#pragma unroll
        for (int kk = 0; kk < 4; kk++) {
            const float s = S[(size_t)(k + kk) * DD + c];
#pragma unroll
            for (int r = 0; r < 16; r++)
                acc[r] = fmaf(rows[r][k + kk], s, acc[r]);
        }
    }

    // q[r] = sum_c rows[r][c] * acc[r][c]  (fixed order: warp shfl + 4-part sum)
#pragma unroll
    for (int r = 0; r < 16; r++) {
        float p = rows[r][c] * acc[r];
#pragma unroll
        for (int o = 16; o > 0; o >>= 1) p += __shfl_down_sync(0xffffffffu, p, o);
        if (lane == 0) parts[wid][r] = p;
    }
    __syncthreads();
    if (c < 16) {
        float q = (parts[0][c] + parts[1][c]) + (parts[2][c] + parts[3][c]);
        if (c < 8) g_qX[rowBase + c] = q;
        else       g_qY[rowBase + c - 8] = q;
    }

#pragma unroll
    for (int r = 0; r < 8; r++) {
        const size_t o = (size_t)(rowBase + r) * DD + c;
        g_Bh[o] = __half_as_ushort(__float2half_rn(rows[r][c]));   // X
        g_Xh[o] = __half_as_ushort(__float2half_rn(acc[r]));       // XS
        g_Ah[o] = __half_as_ushort(__float2half_rn(acc[8 + r]));   // YS
        g_YS[o] = acc[8 + r];
    }
}

// ===========================================================================
// fused: GEMM1 (YS.X^T, fp16 K=128) + exp + GEMM2 (K@XS, fp16) per j-chunk.
// CTA: i-tile 128 x j-slice 1024 (8 chunks of 128). 8 warps, warp = m16.
// ===========================================================================
__global__ __launch_bounds__(256, 1)
void fused_kernel(float* __restrict__ Kout) {
    extern __shared__ char sm[];
    const uint32_t sb = smem_u32(sm);
    float* qy_s = (float*)(sm + SM_QY);

    const int tid  = threadIdx.x;
    const int w    = tid >> 5, lane = tid & 31;
    const int r    = lane >> 2, cp2 = lane & 3;
    const int iBase  = blockIdx.x * 128;
    const int slice  = blockIdx.y;
    const int jBase0 = slice * JSLICE;

    if (tid < 128) qy_s[tid] = 0.5f * g_qY[iBase + tid];

    const int row0 = iBase + w * 16 + r;
    const int lrow = (lane & 15);
    const int lcg  = (lane >> 4) * 16;

    // panel loader: 128 rows x 128 fp16 (256B/row) -> 2 half-slabs of 16KB
    auto load_panel = [&](uint32_t dstBase, const uint16_t* src0) {
#pragma unroll
        for (int k = 0; k < 8; k++) {
            int u = tid + k * 256;
            int row = u >> 4, seg = u & 15;
            uint32_t dst = dstBase + (uint32_t)(seg >> 3) * 16384u +
                           swz((uint32_t)(row * 128 + (seg & 7) * 16));
            CP_ASYNC16(dst, src0 + (size_t)row * DD + seg * 8);
        }
    };
    auto load_chunk = [&](int ch) {
        const int jBase = jBase0 + ch * 128;
        const uint32_t buf = (uint32_t)(ch & 1);
        load_panel(sb + SM_B + buf * 32768u, g_Bh + (size_t)jBase * DD);
        load_panel(sb + SM_XH + buf * 32768u, g_Xh + (size_t)jBase * DD);
        if (tid < 32) CP_ASYNC16(sb + SM_QX + buf * 512u + tid * 16, g_qX + jBase + tid * 4);
    };

    float dP[16][4];
#pragma unroll
    for (int t = 0; t < 16; t++)
#pragma unroll
        for (int v = 0; v < 4; v++) dP[t][v] = 0.f;
    float rs0 = 0.f, rs1 = 0.f;

    // prologue: A panel (chunk-invariant) + chunk 0
    load_panel(sb + SM_A, g_Ah + (size_t)iBase * DD);
    load_chunk(0);
    CP_COMMIT();

    for (int ch = 0; ch < JSLICE / 128; ch++) {
        const int jBase = jBase0 + ch * 128;
        const uint32_t buf = (uint32_t)(ch & 1);
        __syncthreads();                 // all warps done with buf (ch-1)
        if (ch + 1 < JSLICE / 128) load_chunk(ch + 1);
        CP_COMMIT();
        CP_WAIT1();                      // chunk ch (and A) landed
        __syncthreads();

        const float* qx_s = (const float*)(sm + SM_QX + buf * 512u);

        // ---- GEMM1: c = YS . X^T  (K=128, fp16) ----
        float c[16][4];
#pragma unroll
        for (int t = 0; t < 16; t++)
#pragma unroll
            for (int v = 0; v < 4; v++) c[t][v] = 0.f;

#pragma unroll
        for (int half = 0; half < 2; half++) {
            const uint32_t aB = sb + SM_A + (uint32_t)half * 16384u;
            const uint32_t bB = sb + SM_B + buf * 32768u + (uint32_t)half * 16384u;
#pragma unroll
            for (int kk = 0; kk < 4; kk++) {
                uint32_t a0, a1, a2, a3;
                ldsm_x4(a0, a1, a2, a3,
                        aB + swz((uint32_t)((w * 16 + lrow) * 128 + kk * 32 + lcg)));
#pragma unroll
                for (int g = 0; g < 8; g++) {
                    uint32_t b0, b1, b2, b3;
                    ldsm_x4(b0, b1, b2, b3,
                            bB + swz((uint32_t)((g * 16 + lrow) * 128 + kk * 32 + lcg)));
                    mma16816(c[2 * g],     a0, a1, a2, a3, b0, b2);
                    mma16816(c[2 * g + 1], a0, a1, a2, a3, b1, b3);
                }
            }
        }

        // ---- epilogue: K = exp(dot - 0.5*(qY+qX)) ----
        const float qy0 = qy_s[w * 16 + r], qy1 = qy_s[w * 16 + r + 8];
        uint32_t khp[16][2];
#pragma unroll
        for (int t = 0; t < 16; t++) {
            const int jl = t * 8 + cp2 * 2;
            const float qx0 = 0.5f * qx_s[jl], qx1 = 0.5f * qx_s[jl + 1];
            float k00 = __expf(c[t][0] - qy0 - qx0);
            float k01 = __expf(c[t][1] - qy0 - qx1);
            float k10 = __expf(c[t][2] - qy1 - qx0);
            float k11 = __expf(c[t][3] - qy1 - qx1);
            rs0 += k00 + k01;
            rs1 += k10 + k11;
            *(float2*)&Kout[(size_t)row0 * NP + jBase + jl]       = make_float2(k00, k01);
            *(float2*)&Kout[(size_t)(row0 + 8) * NP + jBase + jl] = make_float2(k10, k11);
            khp[t][0] = pack2h(k00, k01);
            khp[t][1] = pack2h(k10, k11);
        }

        // ---- GEMM2: dP += K @ XS  (contract over j-chunk, fp16) ----
#pragma unroll
        for (int kt = 0; kt < 8; kt++) {
            const uint32_t ah0 = khp[2 * kt][0], ah1 = khp[2 * kt][1];
            const uint32_t ah2 = khp[2 * kt + 1][0], ah3 = khp[2 * kt + 1][1];
#pragma unroll
            for (int half2 = 0; half2 < 2; half2++) {
                const uint32_t xB = sb + SM_XH + buf * 32768u + (uint32_t)half2 * 16384u;
#pragma unroll
                for (int dg = 0; dg < 4; dg++) {
                    uint32_t bh0, bh1, bh2, bh3;
                    ldsm_x4t(bh0, bh1, bh2, bh3,
                             xB + swz((uint32_t)((kt * 16 + lrow) * 128 + dg * 32 + lcg)));
                    const int t = half2 * 8 + dg * 2;
                    mma16816(dP[t],     ah0, ah1, ah2, ah3, bh0, bh1);
                    mma16816(dP[t + 1], ah0, ah1, ah2, ah3, bh2, bh3);
                }
            }
        }
    }

    // ---- write dP partials + rowsum partials ----
#pragma unroll
    for (int t = 0; t < 16; t++) {
        const int d = t * 8 + cp2 * 2;
        float* o0 = g_dkp + (size_t)slice * NP * DD + (size_t)row0 * DD + d;
        float* o1 = g_dkp + (size_t)slice * NP * DD + (size_t)(row0 + 8) * DD + d;
        *(float2*)o0 = make_float2(dP[t][0], dP[t][1]);
        *(float2*)o1 = make_float2(dP[t][2], dP[t][3]);
    }
    rs0 += __shfl_xor_sync(0xffffffffu, rs0, 1);
    rs0 += __shfl_xor_sync(0xffffffffu, rs0, 2);
    rs1 += __shfl_xor_sync(0xffffffffu, rs1, 1);
    rs1 += __shfl_xor_sync(0xffffffffu, rs1, 2);
    if (cp2 == 0) {
        g_rsp[(size_t)slice * NP + row0]     = rs0;
        g_rsp[(size_t)slice * NP + row0 + 8] = rs1;
    }
}

// ===========================================================================
__global__ void dk_final_kernel(float* __restrict__ dK) {
    const size_t idx = (size_t)blockIdx.x * 256 + threadIdx.x;
    const size_t i = idx >> 7;
    float s = 0.f, p = 0.f;
#pragma unroll
    for (int h = 0; h < NSLICE; h++) {
        s += g_rsp[(size_t)h * NP + i];
        p += g_dkp[(size_t)h * NP * DD + idx];
    }
    dK[idx] = 2.0f * (s * g_YS[idx] - p);
}

// ===========================================================================
extern "C" void kernel_launch(void* const* d_in, const int* in_sizes, int n_in,
                              void* d_out, int out_size) {
    (void)in_sizes; (void)n_in; (void)out_size;
    const float* X = (const float*)d_in[0];
    const float* Y = (const float*)d_in[1];
    const float* S = (const float*)d_in[2];
    float* out   = (float*)d_out;
    float* Kout  = out;
    float* dKout = out + (size_t)NP * NP;

    cudaFuncSetAttribute(fused_kernel, cudaFuncAttributeMaxDynamicSharedMemorySize, SM_TOTAL);

    prep_kernel<<<NP / 8, 128>>>(X, Y, S);

    dim3 gf(NP / 128, NSLICE);
    fused_kernel<<<gf, 256, SM_TOTAL>>>(Kout);

    dk_final_kernel<<<(NP * DD) / 256, 256>>>(dKout);
}

// round 8
// speedup vs baseline: 8.5619x; 1.0143x over previous
#include <cuda_runtime.h>
#include <cuda_fp16.h>
#include <cstdint>

#define NP 8192
#define DD 128
#define NSLICE 16
#define JSLICE 512

// ---------------- device scratch ----------------
__device__ uint16_t g_Ah[(size_t)NP * DD];      // YS fp16, row-major [i][d]
__device__ uint16_t g_Bh[(size_t)NP * DD];      // X  fp16, row-major [j][d]
__device__ uint16_t g_Xh[(size_t)NP * DD];      // XS fp16, row-major [j][d]
__device__ float    g_YS[(size_t)NP * DD];
__device__ float    g_qX[NP];
__device__ float    g_qY[NP];
__device__ float    g_rsp[(size_t)NSLICE * NP];
__device__ float    g_dkp[(size_t)NSLICE * NP * DD];

// ---------------- helpers ----------------
__device__ __forceinline__ uint32_t smem_u32(const void* p) {
    uint32_t a;
    asm("{ .reg .u64 t; cvta.to.shared.u64 t, %1; cvt.u32.u64 %0, t; }" : "=r"(a) : "l"(p));
    return a;
}
__device__ __forceinline__ uint32_t swz(uint32_t x) { return x ^ ((x >> 3) & 0x70); }

#define CP_ASYNC16(dst, src) \
    asm volatile("cp.async.cg.shared.global [%0], [%1], 16;" :: "r"(dst), "l"(src) : "memory")
#define CP_COMMIT() asm volatile("cp.async.commit_group;" ::: "memory")
#define CP_WAIT1()  asm volatile("cp.async.wait_group 1;" ::: "memory")

__device__ __forceinline__ void ldsm_x4(uint32_t& r0, uint32_t& r1, uint32_t& r2,
                                        uint32_t& r3, uint32_t addr) {
    asm volatile("ldmatrix.sync.aligned.m8n8.x4.shared.b16 {%0,%1,%2,%3}, [%4];"
                 : "=r"(r0), "=r"(r1), "=r"(r2), "=r"(r3) : "r"(addr));
}
__device__ __forceinline__ void ldsm_x4t(uint32_t& r0, uint32_t& r1, uint32_t& r2,
                                         uint32_t& r3, uint32_t addr) {
    asm volatile("ldmatrix.sync.aligned.m8n8.x4.trans.shared.b16 {%0,%1,%2,%3}, [%4];"
                 : "=r"(r0), "=r"(r1), "=r"(r2), "=r"(r3) : "r"(addr));
}
__device__ __forceinline__ void mma16816(float* c, uint32_t a0, uint32_t a1, uint32_t a2,
                                         uint32_t a3, uint32_t b0, uint32_t b1) {
    asm volatile(
        "mma.sync.aligned.m16n8k16.row.col.f32.f16.f16.f32 "
        "{%0,%1,%2,%3}, {%4,%5,%6,%7}, {%8,%9}, {%0,%1,%2,%3};"
        : "+f"(c[0]), "+f"(c[1]), "+f"(c[2]), "+f"(c[3])
        : "r"(a0), "r"(a1), "r"(a2), "r"(a3), "r"(b0), "r"(b1));
}
__device__ __forceinline__ uint32_t pack2h(float a, float b) {
    __half2 h = __floats2half2_rn(a, b);
    return *(uint32_t*)&h;
}
__device__ __forceinline__ void stcs2(float* p, float a, float b) {
    asm volatile("st.global.cs.v2.f32 [%0], {%1, %2};" :: "l"(p), "f"(a), "f"(b) : "memory");
}

// SMEM layout: A panel (chunk-invariant) + double-buffered B/XH/qx
#define SM_A     0u              // 32 KB: YSh [128][128] fp16, 2 half-slabs of 16KB
#define SM_B     32768u          // 2 bufs x 32 KB: Xh panel
#define SM_XH    98304u          // 2 bufs x 32 KB: XSh panel
#define SM_QX    163840u         // 2 bufs x 512
#define SM_QY    164864u         // 512
#define SM_TOTAL 165376

// ===========================================================================
// prep: 256 threads, side-split: threads 0-127 -> 16 X rows, 128-255 -> 16 Y
// rows. 512 blocks. S streamed once per block (broadcast to both halves).
// ===========================================================================
__global__ __launch_bounds__(256, 4)
void prep_kernel(const float* __restrict__ X, const float* __restrict__ Y,
                 const float* __restrict__ S) {
    __shared__ float rows[32][DD];
    __shared__ float parts[8][16];

    const int tid = threadIdx.x;
    const int side = tid >> 7;           // 0 = X, 1 = Y
    const int c = tid & 127;
    const int wid = tid >> 5, lane = tid & 31;
    const int rowBase = blockIdx.x * 16;

#pragma unroll
    for (int r = 0; r < 16; r += 2) {
        const int rr = r + (tid >> 7);   // spread loads over both halves
        rows[rr][c]      = X[(size_t)(rowBase + rr) * DD + c];
        rows[16 + rr][c] = Y[(size_t)(rowBase + rr) * DD + c];
    }
    __syncthreads();

    const float* myrows = &rows[side * 16][0];
    float acc[16];
#pragma unroll
    for (int r = 0; r < 16; r++) acc[r] = 0.f;

    for (int k = 0; k < DD; k += 4) {
#pragma unroll
        for (int kk = 0; kk < 4; kk++) {
            const float s = __ldg(&S[(size_t)(k + kk) * DD + c]);
#pragma unroll
            for (int r = 0; r < 16; r++)
                acc[r] = fmaf(myrows[r * DD + k + kk], s, acc[r]);
        }
    }

    // q[r] = sum_c rows[r][c] * acc[r][c]
#pragma unroll
    for (int r = 0; r < 16; r++) {
        float p = myrows[r * DD + c] * acc[r];
#pragma unroll
        for (int o = 16; o > 0; o >>= 1) p += __shfl_down_sync(0xffffffffu, p, o);
        if (lane == 0) parts[wid][r] = p;
    }
    __syncthreads();
    if (tid < 32) {
        const int s2 = tid >> 4, r = tid & 15;
        float q = (parts[s2 * 4][r] + parts[s2 * 4 + 1][r]) +
                  (parts[s2 * 4 + 2][r] + parts[s2 * 4 + 3][r]);
        if (s2 == 0) g_qX[rowBase + r] = q;
        else         g_qY[rowBase + r] = q;
    }

#pragma unroll
    for (int r = 0; r < 16; r++) {
        const size_t o = (size_t)(rowBase + r) * DD + c;
        if (side == 0) {
            g_Bh[o] = __half_as_ushort(__float2half_rn(myrows[r * DD + c])); // X
            g_Xh[o] = __half_as_ushort(__float2half_rn(acc[r]));             // XS
        } else {
            g_Ah[o] = __half_as_ushort(__float2half_rn(acc[r]));             // YS
            g_YS[o] = acc[r];
        }
    }
}

// ===========================================================================
// fused: GEMM1 (YS.X^T, fp16 K=128) + exp + GEMM2 (K@XS, fp16) per j-chunk.
// CTA: i-tile 128 x j-slice 512 (4 chunks of 128). 8 warps, warp = m16.
// ===========================================================================
__global__ __launch_bounds__(256, 1)
void fused_kernel(float* __restrict__ Kout) {
    extern __shared__ char sm[];
    const uint32_t sb = smem_u32(sm);
    float* qy_s = (float*)(sm + SM_QY);

    const int tid  = threadIdx.x;
    const int w    = tid >> 5, lane = tid & 31;
    const int r    = lane >> 2, cp2 = lane & 3;
    const int iBase  = blockIdx.x * 128;
    const int slice  = blockIdx.y;
    const int jBase0 = slice * JSLICE;

    if (tid < 128) qy_s[tid] = 0.5f * g_qY[iBase + tid];

    const int row0 = iBase + w * 16 + r;
    const int lrow = (lane & 15);
    const int lcg  = (lane >> 4) * 16;

    auto load_panel = [&](uint32_t dstBase, const uint16_t* src0) {
#pragma unroll
        for (int k = 0; k < 8; k++) {
            int u = tid + k * 256;
            int row = u >> 4, seg = u & 15;
            uint32_t dst = dstBase + (uint32_t)(seg >> 3) * 16384u +
                           swz((uint32_t)(row * 128 + (seg & 7) * 16));
            CP_ASYNC16(dst, src0 + (size_t)row * DD + seg * 8);
        }
    };
    auto load_chunk = [&](int ch) {
        const int jBase = jBase0 + ch * 128;
        const uint32_t buf = (uint32_t)(ch & 1);
        load_panel(sb + SM_B + buf * 32768u, g_Bh + (size_t)jBase * DD);
        load_panel(sb + SM_XH + buf * 32768u, g_Xh + (size_t)jBase * DD);
        if (tid < 32) CP_ASYNC16(sb + SM_QX + buf * 512u + tid * 16, g_qX + jBase + tid * 4);
    };

    float dP[16][4];
#pragma unroll
    for (int t = 0; t < 16; t++)
#pragma unroll
        for (int v = 0; v < 4; v++) dP[t][v] = 0.f;
    float rs0 = 0.f, rs1 = 0.f;

    load_panel(sb + SM_A, g_Ah + (size_t)iBase * DD);
    load_chunk(0);
    CP_COMMIT();

    for (int ch = 0; ch < JSLICE / 128; ch++) {
        const int jBase = jBase0 + ch * 128;
        const uint32_t buf = (uint32_t)(ch & 1);
        __syncthreads();
        if (ch + 1 < JSLICE / 128) load_chunk(ch + 1);
        CP_COMMIT();
        CP_WAIT1();
        __syncthreads();

        const float* qx_s = (const float*)(sm + SM_QX + buf * 512u);

        // ---- GEMM1 ----
        float c[16][4];
#pragma unroll
        for (int t = 0; t < 16; t++)
#pragma unroll
            for (int v = 0; v < 4; v++) c[t][v] = 0.f;

#pragma unroll
        for (int half = 0; half < 2; half++) {
            const uint32_t aB = sb + SM_A + (uint32_t)half * 16384u;
            const uint32_t bB = sb + SM_B + buf * 32768u + (uint32_t)half * 16384u;
#pragma unroll
            for (int kk = 0; kk < 4; kk++) {
                uint32_t a0, a1, a2, a3;
                ldsm_x4(a0, a1, a2, a3,
                        aB + swz((uint32_t)((w * 16 + lrow) * 128 + kk * 32 + lcg)));
#pragma unroll
                for (int g = 0; g < 8; g++) {
                    uint32_t b0, b1, b2, b3;
                    ldsm_x4(b0, b1, b2, b3,
                            bB + swz((uint32_t)((g * 16 + lrow) * 128 + kk * 32 + lcg)));
                    mma16816(c[2 * g],     a0, a1, a2, a3, b0, b2);
                    mma16816(c[2 * g + 1], a0, a1, a2, a3, b1, b3);
                }
            }
        }

        // ---- epilogue: K = exp(dot - 0.5*(qY+qX)) ----
        const float qy0 = qy_s[w * 16 + r], qy1 = qy_s[w * 16 + r + 8];
        uint32_t khp[16][2];
#pragma unroll
        for (int t = 0; t < 16; t++) {
            const int jl = t * 8 + cp2 * 2;
            const float qx0 = 0.5f * qx_s[jl], qx1 = 0.5f * qx_s[jl + 1];
            float k00 = __expf(c[t][0] - qy0 - qx0);
            float k01 = __expf(c[t][1] - qy0 - qx1);
            float k10 = __expf(c[t][2] - qy1 - qx0);
            float k11 = __expf(c[t][3] - qy1 - qx1);
            rs0 += k00 + k01;
            rs1 += k10 + k11;
            stcs2(&Kout[(size_t)row0 * NP + jBase + jl], k00, k01);
            stcs2(&Kout[(size_t)(row0 + 8) * NP + jBase + jl], k10, k11);
            khp[t][0] = pack2h(k00, k01);
            khp[t][1] = pack2h(k10, k11);
        }

        // ---- GEMM2: dP += K @ XS ----
#pragma unroll
        for (int kt = 0; kt < 8; kt++) {
            const uint32_t ah0 = khp[2 * kt][0], ah1 = khp[2 * kt][1];
            const uint32_t ah2 = khp[2 * kt + 1][0], ah3 = khp[2 * kt + 1][1];
#pragma unroll
            for (int half2 = 0; half2 < 2; half2++) {
                const uint32_t xB = sb + SM_XH + buf * 32768u + (uint32_t)half2 * 16384u;
#pragma unroll
                for (int dg = 0; dg < 4; dg++) {
                    uint32_t bh0, bh1, bh2, bh3;
                    ldsm_x4t(bh0, bh1, bh2, bh3,
                             xB + swz((uint32_t)((kt * 16 + lrow) * 128 + dg * 32 + lcg)));
                    const int t = half2 * 8 + dg * 2;
                    mma16816(dP[t],     ah0, ah1, ah2, ah3, bh0, bh1);
                    mma16816(dP[t + 1], ah0, ah1, ah2, ah3, bh2, bh3);
                }
            }
        }
    }

    // ---- write dP partials + rowsum partials ----
#pragma unroll
    for (int t = 0; t < 16; t++) {
        const int d = t * 8 + cp2 * 2;
        float* o0 = g_dkp + (size_t)slice * NP * DD + (size_t)row0 * DD + d;
        float* o1 = g_dkp + (size_t)slice * NP * DD + (size_t)(row0 + 8) * DD + d;
        stcs2(o0, dP[t][0], dP[t][1]);
        stcs2(o1, dP[t][2], dP[t][3]);
    }
    rs0 += __shfl_xor_sync(0xffffffffu, rs0, 1);
    rs0 += __shfl_xor_sync(0xffffffffu, rs0, 2);
    rs1 += __shfl_xor_sync(0xffffffffu, rs1, 1);
    rs1 += __shfl_xor_sync(0xffffffffu, rs1, 2);
    if (cp2 == 0) {
        g_rsp[(size_t)slice * NP + row0]     = rs0;
        g_rsp[(size_t)slice * NP + row0 + 8] = rs1;
    }
}

// ===========================================================================
__global__ void dk_final_kernel(float* __restrict__ dK) {
    const size_t idx = (size_t)blockIdx.x * 256 + threadIdx.x;
    const size_t i = idx >> 7;
    float s = 0.f, p = 0.f;
#pragma unroll
    for (int h = 0; h < NSLICE; h++) {
        s += g_rsp[(size_t)h * NP + i];
        p += g_dkp[(size_t)h * NP * DD + idx];
    }
    dK[idx] = 2.0f * (s * g_YS[idx] - p);
}

// ===========================================================================
extern "C" void kernel_launch(void* const* d_in, const int* in_sizes, int n_in,
                              void* d_out, int out_size) {
    (void)in_sizes; (void)n_in; (void)out_size;
    const float* X = (const float*)d_in[0];
    const float* Y = (const float*)d_in[1];
    const float* S = (const float*)d_in[2];
    float* out   = (float*)d_out;
    float* Kout  = out;
    float* dKout = out + (size_t)NP * NP;

    cudaFuncSetAttribute(fused_kernel, cudaFuncAttributeMaxDynamicSharedMemorySize, SM_TOTAL);

    prep_kernel<<<NP / 16, 256>>>(X, Y, S);

    dim3 gf(NP / 128, NSLICE);
    fused_kernel<<<gf, 256, SM_TOTAL>>>(Kout);

    dk_final_kernel<<<(NP * DD) / 256, 256>>>(dKout);
}